// round 12
// baseline (speedup 1.0000x reference)
#include <cuda_runtime.h>
#include <cuda_fp16.h>
#include <cstdint>

#define Bb 8
#define Nn 1024
#define Ff 256
#define Hh 4
#define Uu 256
#define BHt (Bb * Hh)

#define STRIDE 40   // smem row stride in halves (80B): conflict-free for ldmatrix

// ---------------- device scratch (static, no allocation) ----------------
__device__ __half g_xh[(size_t)Bb * Nn * Ff];       // x fp16 [b][n][f]
__device__ __half g_vt[(size_t)BHt * Uu * Nn];      // h^T fp16 [bh][u][n]
__device__ __half g_wt_hi[Hh * Uu * Ff];            // W^T split fp16 [h][u][f]
__device__ __half g_wt_lo[Hh * Uu * Ff];
__device__ float g_srcp[2 * BHt * Nn];
__device__ float g_dstp[2 * BHt * Nn];
__device__ __half g_Qh[BHt * Nn];
__device__ __half g_Sh[BHt * Nn];
__device__ __half g_Dh[BHt * Nn];
__device__ __half g_Ph[BHt * Nn];
__device__ __half g_Rh[BHt * Nn];
__device__ __half g_Th[BHt * Nn];
__device__ float g_inv[BHt * Nn];                   // 1 / rowsum

// ---------------- PTX helpers ----------------
__device__ __forceinline__ void mma16816(float* c, const uint32_t* a, uint32_t b0, uint32_t b1) {
    asm volatile(
        "mma.sync.aligned.m16n8k16.row.col.f32.f16.f16.f32 "
        "{%0,%1,%2,%3}, {%4,%5,%6,%7}, {%8,%9}, {%0,%1,%2,%3};"
        : "+f"(c[0]), "+f"(c[1]), "+f"(c[2]), "+f"(c[3])
        : "r"(a[0]), "r"(a[1]), "r"(a[2]), "r"(a[3]), "r"(b0), "r"(b1));
}
__device__ __forceinline__ void ldm_x4(uint32_t* r, uint32_t addr) {
    asm volatile("ldmatrix.sync.aligned.m8n8.x4.shared.b16 {%0,%1,%2,%3}, [%4];"
                 : "=r"(r[0]), "=r"(r[1]), "=r"(r[2]), "=r"(r[3]) : "r"(addr));
}
__device__ __forceinline__ void cp16(uint32_t dst, const void* src) {
    asm volatile("cp.async.ca.shared.global [%0], [%1], 16;" :: "r"(dst), "l"(src));
}
__device__ __forceinline__ void cp_commit() { asm volatile("cp.async.commit_group;"); }
template <int N> __device__ __forceinline__ void cp_wait() {
    asm volatile("cp.async.wait_group %0;" :: "n"(N));
}

// ================== prep: x -> fp16 ==================
__global__ __launch_bounds__(256) void prep_x_kernel(const float* __restrict__ x) {
    int idx = blockIdx.x * 256 + threadIdx.x;          // float4 index
    float4 v = ((const float4*)x)[idx];
    __half2 hi01 = __floats2half2_rn(v.x, v.y);
    __half2 hi23 = __floats2half2_rn(v.z, v.w);
    ((__half2*)g_xh)[idx * 2] = hi01;
    ((__half2*)g_xh)[idx * 2 + 1] = hi23;
}

// ================== prep: W^T split fp16 [h][u][f] ==================
__global__ __launch_bounds__(256) void prep_wt_kernel(const float* __restrict__ W) {
    int idx = blockIdx.x * 256 + threadIdx.x;
    int f = idx & 255, u = (idx >> 8) & 255, h = idx >> 16;
    float w = W[((size_t)(h * 256 + f)) * 256 + u];
    __half hi = __float2half_rn(w);
    __half lo = __float2half_rn(w - __half2float(hi));
    size_t o = ((size_t)(h * 256 + u)) * 256 + f;
    g_wt_hi[o] = hi;
    g_wt_lo[o] = lo;
}

// ================== proj: h = xh @ (WH + WL)  — 2 MMA terms ==================
#define PBUF (3 * 128 * STRIDE * 2)                    // 30720 B per buffer
#define P_SMEM (2 * PBUF + 4096)

__global__ __launch_bounds__(256) void proj_mma_kernel(const float* __restrict__ a_src,
                                                       const float* __restrict__ a_dst) {
    extern __shared__ __align__(16) char dyn[];
    float* sred = (float*)(dyn + 2 * PBUF);

    int tid = threadIdx.x;
    int warp = tid >> 5, lane = tid & 31;
    int warp_m = warp & 3, warp_n = warp >> 2;
    int bh = blockIdx.z, b = bh >> 2, h = bh & 3;
    int i0 = blockIdx.x * 128, u0 = blockIdx.y * 128;

    uint32_t smb = (uint32_t)__cvta_generic_to_shared(dyn);
    int row = tid >> 1, seg = tid & 1;

    auto issue = [&](int st, int bufi) {
        int f0 = st * 32;
        uint32_t base = smb + bufi * PBUF + row * (STRIDE * 2) + seg * 32;
        const __half* gA  = g_xh + ((size_t)(b * Nn + i0 + row)) * Ff + f0 + seg * 16;
        const __half* gWh = g_wt_hi + ((size_t)(h * 256 + u0 + row)) * 256 + f0 + seg * 16;
        const __half* gWl = g_wt_lo + ((size_t)(h * 256 + u0 + row)) * 256 + f0 + seg * 16;
        cp16(base, gA);                 cp16(base + 16, gA + 8);
        cp16(base + 10240, gWh);        cp16(base + 10240 + 16, gWh + 8);
        cp16(base + 20480, gWl);        cp16(base + 20480 + 16, gWl + 8);
    };

    float acc[2][8][4];
#pragma unroll
    for (int mt = 0; mt < 2; mt++)
#pragma unroll
        for (int nt = 0; nt < 8; nt++)
#pragma unroll
            for (int q = 0; q < 4; q++) acc[mt][nt][q] = 0.f;

    issue(0, 0);
    cp_commit();

    uint32_t a_off = (uint32_t)(warp_m * 32 + (lane & 15)) * (STRIDE * 2) + ((lane >> 4) * 8) * 2;
    uint32_t b_off = (uint32_t)(warp_n * 64 + (lane & 7)) * (STRIDE * 2) + ((lane >> 3) * 8) * 2;

    for (int st = 0; st < 8; st++) {
        if (st < 7) { issue(st + 1, (st + 1) & 1); cp_commit(); cp_wait<1>(); }
        else cp_wait<0>();
        __syncthreads();

        uint32_t bb = smb + (st & 1) * PBUF;
        uint32_t aH[2][2][4];
#pragma unroll
        for (int mt = 0; mt < 2; mt++)
#pragma unroll
            for (int kk = 0; kk < 2; kk++)
                ldm_x4(aH[mt][kk], bb + a_off + mt * 16 * (STRIDE * 2) + kk * 32);
#pragma unroll
        for (int nt = 0; nt < 8; nt++) {
            uint32_t bH[4], bL[4];
            uint32_t bd = bb + 10240 + b_off + nt * 8 * (STRIDE * 2);
            ldm_x4(bH, bd);
            ldm_x4(bL, bd + 10240);
#pragma unroll
            for (int kk = 0; kk < 2; kk++)
#pragma unroll
                for (int mt = 0; mt < 2; mt++) {
                    mma16816(acc[mt][nt], aH[mt][kk], bH[2 * kk], bH[2 * kk + 1]);
                    mma16816(acc[mt][nt], aH[mt][kk], bL[2 * kk], bL[2 * kk + 1]);
                }
        }
        __syncthreads();
    }

    // ---- epilogue A: partial src/dst dots ----
    {
        float s1[4] = {0.f, 0.f, 0.f, 0.f};
        float s2[4] = {0.f, 0.f, 0.f, 0.f};
#pragma unroll
        for (int nt = 0; nt < 8; nt++) {
            int u = u0 + warp_n * 64 + nt * 8 + (lane & 3) * 2;
            float2 as = *(const float2*)&a_src[h * 256 + u];
            float2 ad = *(const float2*)&a_dst[h * 256 + u];
#pragma unroll
            for (int mt = 0; mt < 2; mt++) {
                s1[mt * 2 + 0] += acc[mt][nt][0] * as.x + acc[mt][nt][1] * as.y;
                s1[mt * 2 + 1] += acc[mt][nt][2] * as.x + acc[mt][nt][3] * as.y;
                s2[mt * 2 + 0] += acc[mt][nt][0] * ad.x + acc[mt][nt][1] * ad.y;
                s2[mt * 2 + 1] += acc[mt][nt][2] * ad.x + acc[mt][nt][3] * ad.y;
            }
        }
#pragma unroll
        for (int q = 0; q < 4; q++) {
            s1[q] += __shfl_xor_sync(0xffffffffu, s1[q], 1);
            s1[q] += __shfl_xor_sync(0xffffffffu, s1[q], 2);
            s2[q] += __shfl_xor_sync(0xffffffffu, s2[q], 1);
            s2[q] += __shfl_xor_sync(0xffffffffu, s2[q], 2);
        }
        if ((lane & 3) == 0) {
#pragma unroll
            for (int q = 0; q < 4; q++) {
                int r = warp_m * 32 + (q >> 1) * 16 + (q & 1) * 8 + (lane >> 2);
                sred[(0 * 2 + warp_n) * 128 + r] = s1[q];
                sred[(2 + warp_n) * 128 + r] = s2[q];
            }
        }
    }
    __syncthreads();
    if (tid < 128) {
        size_t o = (size_t)blockIdx.y * (BHt * Nn) + bh * Nn + i0 + tid;
        g_srcp[o] = sred[0 * 128 + tid] + sred[1 * 128 + tid];
        g_dstp[o] = sred[2 * 128 + tid] + sred[3 * 128 + tid];
    }
    __syncthreads();

    // ---- epilogue B: fp16 transpose restage -> g_vt [u][n] ----
    __half (*tr)[136] = (__half (*)[136])dyn;
#pragma unroll
    for (int mt = 0; mt < 2; mt++) {
        int i_loc = warp_m * 32 + mt * 16 + (lane >> 2);
#pragma unroll
        for (int nt = 0; nt < 8; nt++) {
            int u_loc = warp_n * 64 + nt * 8 + (lane & 3) * 2;
            tr[u_loc][i_loc]         = __float2half_rn(acc[mt][nt][0]);
            tr[u_loc + 1][i_loc]     = __float2half_rn(acc[mt][nt][1]);
            tr[u_loc][i_loc + 8]     = __float2half_rn(acc[mt][nt][2]);
            tr[u_loc + 1][i_loc + 8] = __float2half_rn(acc[mt][nt][3]);
        }
    }
    __syncthreads();
    {
        const float4* srcp = (const float4*)&tr[row][seg * 64];
        float4* dstp = (float4*)&g_vt[((size_t)bh * Uu + u0 + row) * Nn + i0 + seg * 64];
#pragma unroll
        for (int k = 0; k < 8; k++) dstp[k] = srcp[k];
    }
}

// ================== prep: combine partials, P/Q/R/S/thr fp16 per (b,h) ==================
__global__ __launch_bounds__(1024) void prep_pqrs_kernel() {
    __shared__ float red[1024];
    int bh = blockIdx.x, tid = threadIdx.x;
    int row = bh * Nn + tid;
    float d = g_dstp[row] + g_dstp[BHt * Nn + row];
    float sv = g_srcp[row] + g_srcp[BHt * Nn + row];
    red[tid] = d;
    __syncthreads();
    for (int s = 512; s > 0; s >>= 1) {
        if (tid < s) red[tid] = fmaxf(red[tid], red[tid + s]);
        __syncthreads();
    }
    float dmax = red[0];
    g_Qh[row] = __float2half_rn(__expf(d - dmax));
    g_Sh[row] = __float2half_rn(__expf(0.2f * (d - dmax)));
    g_Dh[row] = __float2half_rn(d);
    float T = sv + dmax;
    float m = fmaxf(T, 0.2f * T);
    g_Ph[row] = __float2half_rn(__expf(T - m));
    g_Rh[row] = __float2half_rn(__expf(0.2f * T - m));
    g_Th[row] = __float2half_rn(-sv);
}

// ================== rowsum: den_i via the IDENTICAL fp16 weight pipeline ==================
// One warp per row. Same inputs, same half2 ops as attn's weight-gen, so the
// summed values are bit-identical to the MMA A-fragments (common-mode cancel).
__global__ __launch_bounds__(256) void rowsum_kernel() {
    int warp = threadIdx.x >> 5, lane = threadIdx.x & 31;
    int row = blockIdx.x * 8 + warp;                   // [0, BHt*Nn)
    int bh = row >> 10;

    __half2 P = __half2half2(g_Ph[row]);
    __half2 R = __half2half2(g_Rh[row]);
    __half2 T = __half2half2(g_Th[row]);
    const __half2* D2 = (const __half2*)(g_Dh + bh * Nn);
    const __half2* Q2 = (const __half2*)(g_Qh + bh * Nn);
    const __half2* S2 = (const __half2*)(g_Sh + bh * Nn);

    float s = 0.f;
#pragma unroll
    for (int k = 0; k < 16; k++) {
        int j2 = lane + k * 32;                        // half2 index, [0, 512)
        __half2 D = D2[j2], Q = Q2[j2], S = S2[j2];
        __half2 mA = __hge2(D, T);
        __half2 wP = __hmul2(P, Q);
        __half2 wR = __hmul2(R, S);
        __half2 w = __hfma2(__hsub2(wP, wR), mA, wR);
        float2 f = __half22float2(w);
        s += f.x + f.y;
    }
#pragma unroll
    for (int o = 16; o > 0; o >>= 1) s += __shfl_down_sync(0xffffffffu, s, o);
    if (lane == 0) g_inv[row] = 1.0f / s;
}

// ================== attention: half2 weight-gen + ldmatrix V, rowsum removed ==================
__global__ __launch_bounds__(256) void attn_mma_kernel(float* __restrict__ out) {
    __shared__ __align__(16) __half VT[2][128][STRIDE];
    __shared__ __half Dsh[Nn], Qsh[Nn], Ssh[Nn];
    __shared__ __half Pn[128], Rn[128], Tn[128];
    __shared__ float In[128];

    int tid = threadIdx.x;
    int warp = tid >> 5, lane = tid & 31;
    int warp_m = warp & 3, warp_n = warp >> 2;
    int bh = blockIdx.z, b = bh >> 2, h = bh & 3;
    int i0 = blockIdx.x * 128, u0 = blockIdx.y * 128;

    for (int j = tid; j < Nn; j += 256) {
        Dsh[j] = g_Dh[bh * Nn + j];
        Qsh[j] = g_Qh[bh * Nn + j];
        Ssh[j] = g_Sh[bh * Nn + j];
    }
    if (tid < 128) {
        Pn[tid] = g_Ph[bh * Nn + i0 + tid];
        Rn[tid] = g_Rh[bh * Nn + i0 + tid];
        Tn[tid] = g_Th[bh * Nn + i0 + tid];
        In[tid] = g_inv[bh * Nn + i0 + tid];
    }

    int row = tid >> 1, seg = tid & 1;
    uint32_t vt0 = (uint32_t)__cvta_generic_to_shared(&VT[0][0][0]);
    const uint32_t VBUF = 128 * STRIDE * 2;

    auto issue = [&](int st, int bufi) {
        int j0 = st * 32;
        uint32_t d = vt0 + bufi * VBUF + row * (STRIDE * 2) + seg * 32;
        const __half* g = g_vt + ((size_t)bh * Uu + u0 + row) * Nn + j0 + seg * 16;
        cp16(d, g);
        cp16(d + 16, g + 8);
    };

    float acc[2][8][4];
#pragma unroll
    for (int mt = 0; mt < 2; mt++)
#pragma unroll
        for (int nt = 0; nt < 8; nt++)
#pragma unroll
            for (int q = 0; q < 4; q++) acc[mt][nt][q] = 0.f;

    issue(0, 0);
    cp_commit();
    __syncthreads();

    __half2 Pv[4], Rv[4], Tv[4];
#pragma unroll
    for (int q = 0; q < 4; q++) {
        int r = warp_m * 32 + (q >> 1) * 16 + (q & 1) * 8 + (lane >> 2);
        Pv[q] = __half2half2(Pn[r]);
        Rv[q] = __half2half2(Rn[r]);
        Tv[q] = __half2half2(Tn[r]);
    }

    uint32_t b_off = (uint32_t)(warp_n * 64 + (lane & 7)) * (STRIDE * 2) + ((lane >> 3) * 8) * 2;

    for (int st = 0; st < 32; st++) {
        int j0 = st * 32;
        if (st < 31) { issue(st + 1, (st + 1) & 1); cp_commit(); cp_wait<1>(); }
        else cp_wait<0>();
        __syncthreads();

        uint32_t bb = vt0 + (st & 1) * VBUF;
        uint32_t bfr[8][4];
#pragma unroll
        for (int nt = 0; nt < 8; nt++)
            ldm_x4(bfr[nt], bb + b_off + nt * 8 * (STRIDE * 2));

#pragma unroll
        for (int kk = 0; kk < 2; kk++) {
            int c = j0 + kk * 16 + (lane & 3) * 2;
            __half2 Qa = *(const __half2*)&Qsh[c], Qb = *(const __half2*)&Qsh[c + 8];
            __half2 Sa = *(const __half2*)&Ssh[c], Sb = *(const __half2*)&Ssh[c + 8];
            __half2 Da = *(const __half2*)&Dsh[c], Db = *(const __half2*)&Dsh[c + 8];

            uint32_t aW[2][4];
#pragma unroll
            for (int mt = 0; mt < 2; mt++) {
#pragma unroll
                for (int dq = 0; dq < 2; dq++) {
                    int q = mt * 2 + dq;
                    __half2 mA = __hge2(Da, Tv[q]);
                    __half2 wPa = __hmul2(Pv[q], Qa);
                    __half2 wRa = __hmul2(Rv[q], Sa);
                    __half2 wa = __hfma2(__hsub2(wPa, wRa), mA, wRa);
                    __half2 mB = __hge2(Db, Tv[q]);
                    __half2 wPb = __hmul2(Pv[q], Qb);
                    __half2 wRb = __hmul2(Rv[q], Sb);
                    __half2 wb = __hfma2(__hsub2(wPb, wRb), mB, wRb);
                    aW[mt][dq]     = *reinterpret_cast<uint32_t*>(&wa);
                    aW[mt][dq + 2] = *reinterpret_cast<uint32_t*>(&wb);
                }
            }
#pragma unroll
            for (int nt = 0; nt < 8; nt++)
#pragma unroll
                for (int mt = 0; mt < 2; mt++)
                    mma16816(acc[mt][nt], aW[mt], bfr[nt][2 * kk], bfr[nt][2 * kk + 1]);
        }
        __syncthreads();
    }

#pragma unroll
    for (int mt = 0; mt < 2; mt++) {
        int rl = warp_m * 32 + mt * 16 + (lane >> 2);
        int i_lo = i0 + rl;
        float inv0 = In[rl], inv1 = In[rl + 8];
#pragma unroll
        for (int nt = 0; nt < 8; nt++) {
            int u = u0 + warp_n * 64 + nt * 8 + (lane & 3) * 2;
            size_t o0 = ((size_t)(b * Nn + i_lo)) * (Hh * Uu) + h * Uu + u;
            size_t o1 = ((size_t)(b * Nn + i_lo + 8)) * (Hh * Uu) + h * Uu + u;
            *(float2*)&out[o0] = make_float2(acc[mt][nt][0] * inv0, acc[mt][nt][1] * inv0);
            *(float2*)&out[o1] = make_float2(acc[mt][nt][2] * inv1, acc[mt][nt][3] * inv1);
        }
    }
}

// ---------------------------------------------------------------------------
extern "C" void kernel_launch(void* const* d_in, const int* in_sizes, int n_in,
                              void* d_out, int out_size) {
    (void)in_sizes; (void)n_in; (void)out_size;
    const float* x     = (const float*)d_in[0];
    const float* W     = (const float*)d_in[1];
    const float* a_src = (const float*)d_in[2];
    const float* a_dst = (const float*)d_in[3];
    float* out = (float*)d_out;

    cudaFuncSetAttribute(proj_mma_kernel, cudaFuncAttributeMaxDynamicSharedMemorySize, P_SMEM);

    prep_x_kernel<<<(Bb * Nn * Ff) / 1024, 256>>>(x);
    prep_wt_kernel<<<(Hh * Uu * Ff) / 256, 256>>>(W);
    proj_mma_kernel<<<dim3(8, 2, BHt), 256, P_SMEM>>>(a_src, a_dst);
    prep_pqrs_kernel<<<BHt, 1024>>>();
    rowsum_kernel<<<(BHt * Nn) / 8, 256>>>();
    attn_mma_kernel<<<dim3(8, 2, BHt), 256>>>(out);
}

// round 13
// speedup vs baseline: 1.0375x; 1.0375x over previous
#include <cuda_runtime.h>
#include <cuda_fp16.h>
#include <cstdint>

#define Bb 8
#define Nn 1024
#define Ff 256
#define Hh 4
#define Uu 256
#define BHt (Bb * Hh)

#define STRIDE 40    // proj smem row stride in halves (80B)
#define VSTR 72      // attn V row stride in halves (144B): 9r mod 8 distinct -> conflict-free

// ---------------- device scratch (static, no allocation) ----------------
__device__ __half g_xh[(size_t)Bb * Nn * Ff];       // x fp16 [b][n][f]
__device__ __half g_vt[(size_t)BHt * Uu * Nn];      // h^T fp16 [bh][u][n]
__device__ __half g_wt_hi[Hh * Uu * Ff];            // W^T split fp16 [h][u][f]
__device__ __half g_wt_lo[Hh * Uu * Ff];
__device__ float g_srcp[2 * BHt * Nn];
__device__ float g_dstp[2 * BHt * Nn];
__device__ __half g_Qh[BHt * Nn];
__device__ __half g_Sh[BHt * Nn];
__device__ __half g_Dh[BHt * Nn];
__device__ __half g_Ph[BHt * Nn];
__device__ __half g_Rh[BHt * Nn];
__device__ __half g_Th[BHt * Nn];

// ---------------- PTX helpers ----------------
__device__ __forceinline__ void mma16816(float* c, const uint32_t* a, uint32_t b0, uint32_t b1) {
    asm volatile(
        "mma.sync.aligned.m16n8k16.row.col.f32.f16.f16.f32 "
        "{%0,%1,%2,%3}, {%4,%5,%6,%7}, {%8,%9}, {%0,%1,%2,%3};"
        : "+f"(c[0]), "+f"(c[1]), "+f"(c[2]), "+f"(c[3])
        : "r"(a[0]), "r"(a[1]), "r"(a[2]), "r"(a[3]), "r"(b0), "r"(b1));
}
__device__ __forceinline__ void ldm_x4(uint32_t* r, uint32_t addr) {
    asm volatile("ldmatrix.sync.aligned.m8n8.x4.shared.b16 {%0,%1,%2,%3}, [%4];"
                 : "=r"(r[0]), "=r"(r[1]), "=r"(r[2]), "=r"(r[3]) : "r"(addr));
}
__device__ __forceinline__ void cp16(uint32_t dst, const void* src) {
    asm volatile("cp.async.ca.shared.global [%0], [%1], 16;" :: "r"(dst), "l"(src));
}
__device__ __forceinline__ void cp_commit() { asm volatile("cp.async.commit_group;"); }
template <int N> __device__ __forceinline__ void cp_wait() {
    asm volatile("cp.async.wait_group %0;" :: "n"(N));
}

// ================== prep: x -> fp16 ==================
__global__ __launch_bounds__(256) void prep_x_kernel(const float* __restrict__ x) {
    int idx = blockIdx.x * 256 + threadIdx.x;          // float4 index
    float4 v = ((const float4*)x)[idx];
    __half2 hi01 = __floats2half2_rn(v.x, v.y);
    __half2 hi23 = __floats2half2_rn(v.z, v.w);
    ((__half2*)g_xh)[idx * 2] = hi01;
    ((__half2*)g_xh)[idx * 2 + 1] = hi23;
}

// ================== prep: W^T split fp16 [h][u][f] ==================
__global__ __launch_bounds__(256) void prep_wt_kernel(const float* __restrict__ W) {
    int idx = blockIdx.x * 256 + threadIdx.x;
    int f = idx & 255, u = (idx >> 8) & 255, h = idx >> 16;
    float w = W[((size_t)(h * 256 + f)) * 256 + u];
    __half hi = __float2half_rn(w);
    __half lo = __float2half_rn(w - __half2float(hi));
    size_t o = ((size_t)(h * 256 + u)) * 256 + f;
    g_wt_hi[o] = hi;
    g_wt_lo[o] = lo;
}

// ================== proj (R11, unchanged): h = xh @ (WH + WL) ==================
#define PBUF (3 * 128 * STRIDE * 2)                    // 30720 B per buffer
#define P_SMEM (2 * PBUF + 4096)

__global__ __launch_bounds__(256) void proj_mma_kernel(const float* __restrict__ a_src,
                                                       const float* __restrict__ a_dst) {
    extern __shared__ __align__(16) char dyn[];
    float* sred = (float*)(dyn + 2 * PBUF);

    int tid = threadIdx.x;
    int warp = tid >> 5, lane = tid & 31;
    int warp_m = warp & 3, warp_n = warp >> 2;
    int bh = blockIdx.z, b = bh >> 2, h = bh & 3;
    int i0 = blockIdx.x * 128, u0 = blockIdx.y * 128;

    uint32_t smb = (uint32_t)__cvta_generic_to_shared(dyn);
    int row = tid >> 1, seg = tid & 1;

    auto issue = [&](int st, int bufi) {
        int f0 = st * 32;
        uint32_t base = smb + bufi * PBUF + row * (STRIDE * 2) + seg * 32;
        const __half* gA  = g_xh + ((size_t)(b * Nn + i0 + row)) * Ff + f0 + seg * 16;
        const __half* gWh = g_wt_hi + ((size_t)(h * 256 + u0 + row)) * 256 + f0 + seg * 16;
        const __half* gWl = g_wt_lo + ((size_t)(h * 256 + u0 + row)) * 256 + f0 + seg * 16;
        cp16(base, gA);                 cp16(base + 16, gA + 8);
        cp16(base + 10240, gWh);        cp16(base + 10240 + 16, gWh + 8);
        cp16(base + 20480, gWl);        cp16(base + 20480 + 16, gWl + 8);
    };

    float acc[2][8][4];
#pragma unroll
    for (int mt = 0; mt < 2; mt++)
#pragma unroll
        for (int nt = 0; nt < 8; nt++)
#pragma unroll
            for (int q = 0; q < 4; q++) acc[mt][nt][q] = 0.f;

    issue(0, 0);
    cp_commit();

    uint32_t a_off = (uint32_t)(warp_m * 32 + (lane & 15)) * (STRIDE * 2) + ((lane >> 4) * 8) * 2;
    uint32_t b_off = (uint32_t)(warp_n * 64 + (lane & 7)) * (STRIDE * 2) + ((lane >> 3) * 8) * 2;

    for (int st = 0; st < 8; st++) {
        if (st < 7) { issue(st + 1, (st + 1) & 1); cp_commit(); cp_wait<1>(); }
        else cp_wait<0>();
        __syncthreads();

        uint32_t bb = smb + (st & 1) * PBUF;
        uint32_t aH[2][2][4];
#pragma unroll
        for (int mt = 0; mt < 2; mt++)
#pragma unroll
            for (int kk = 0; kk < 2; kk++)
                ldm_x4(aH[mt][kk], bb + a_off + mt * 16 * (STRIDE * 2) + kk * 32);
#pragma unroll
        for (int nt = 0; nt < 8; nt++) {
            uint32_t bH[4], bL[4];
            uint32_t bd = bb + 10240 + b_off + nt * 8 * (STRIDE * 2);
            ldm_x4(bH, bd);
            ldm_x4(bL, bd + 10240);
#pragma unroll
            for (int kk = 0; kk < 2; kk++)
#pragma unroll
                for (int mt = 0; mt < 2; mt++) {
                    mma16816(acc[mt][nt], aH[mt][kk], bH[2 * kk], bH[2 * kk + 1]);
                    mma16816(acc[mt][nt], aH[mt][kk], bL[2 * kk], bL[2 * kk + 1]);
                }
        }
        __syncthreads();
    }

    // ---- epilogue A: partial src/dst dots ----
    {
        float s1[4] = {0.f, 0.f, 0.f, 0.f};
        float s2[4] = {0.f, 0.f, 0.f, 0.f};
#pragma unroll
        for (int nt = 0; nt < 8; nt++) {
            int u = u0 + warp_n * 64 + nt * 8 + (lane & 3) * 2;
            float2 as = *(const float2*)&a_src[h * 256 + u];
            float2 ad = *(const float2*)&a_dst[h * 256 + u];
#pragma unroll
            for (int mt = 0; mt < 2; mt++) {
                s1[mt * 2 + 0] += acc[mt][nt][0] * as.x + acc[mt][nt][1] * as.y;
                s1[mt * 2 + 1] += acc[mt][nt][2] * as.x + acc[mt][nt][3] * as.y;
                s2[mt * 2 + 0] += acc[mt][nt][0] * ad.x + acc[mt][nt][1] * ad.y;
                s2[mt * 2 + 1] += acc[mt][nt][2] * ad.x + acc[mt][nt][3] * ad.y;
            }
        }
#pragma unroll
        for (int q = 0; q < 4; q++) {
            s1[q] += __shfl_xor_sync(0xffffffffu, s1[q], 1);
            s1[q] += __shfl_xor_sync(0xffffffffu, s1[q], 2);
            s2[q] += __shfl_xor_sync(0xffffffffu, s2[q], 1);
            s2[q] += __shfl_xor_sync(0xffffffffu, s2[q], 2);
        }
        if ((lane & 3) == 0) {
#pragma unroll
            for (int q = 0; q < 4; q++) {
                int r = warp_m * 32 + (q >> 1) * 16 + (q & 1) * 8 + (lane >> 2);
                sred[(0 * 2 + warp_n) * 128 + r] = s1[q];
                sred[(2 + warp_n) * 128 + r] = s2[q];
            }
        }
    }
    __syncthreads();
    if (tid < 128) {
        size_t o = (size_t)blockIdx.y * (BHt * Nn) + bh * Nn + i0 + tid;
        g_srcp[o] = sred[0 * 128 + tid] + sred[1 * 128 + tid];
        g_dstp[o] = sred[2 * 128 + tid] + sred[3 * 128 + tid];
    }
    __syncthreads();

    // ---- epilogue B: fp16 transpose restage -> g_vt [u][n] ----
    __half (*tr)[136] = (__half (*)[136])dyn;
#pragma unroll
    for (int mt = 0; mt < 2; mt++) {
        int i_loc = warp_m * 32 + mt * 16 + (lane >> 2);
#pragma unroll
        for (int nt = 0; nt < 8; nt++) {
            int u_loc = warp_n * 64 + nt * 8 + (lane & 3) * 2;
            tr[u_loc][i_loc]         = __float2half_rn(acc[mt][nt][0]);
            tr[u_loc + 1][i_loc]     = __float2half_rn(acc[mt][nt][1]);
            tr[u_loc][i_loc + 8]     = __float2half_rn(acc[mt][nt][2]);
            tr[u_loc + 1][i_loc + 8] = __float2half_rn(acc[mt][nt][3]);
        }
    }
    __syncthreads();
    {
        const float4* srcp = (const float4*)&tr[row][seg * 64];
        float4* dstp = (float4*)&g_vt[((size_t)bh * Uu + u0 + row) * Nn + i0 + seg * 64];
#pragma unroll
        for (int k = 0; k < 8; k++) dstp[k] = srcp[k];
    }
}

// ================== prep: combine partials, P/Q/R/S/thr fp16 per (b,h) ==================
__global__ __launch_bounds__(1024) void prep_pqrs_kernel() {
    __shared__ float red[1024];
    int bh = blockIdx.x, tid = threadIdx.x;
    int row = bh * Nn + tid;
    float d = g_dstp[row] + g_dstp[BHt * Nn + row];
    float sv = g_srcp[row] + g_srcp[BHt * Nn + row];
    red[tid] = d;
    __syncthreads();
    for (int s = 512; s > 0; s >>= 1) {
        if (tid < s) red[tid] = fmaxf(red[tid], red[tid + s]);
        __syncthreads();
    }
    float dmax = red[0];
    g_Qh[row] = __float2half_rn(__expf(d - dmax));
    g_Sh[row] = __float2half_rn(__expf(0.2f * (d - dmax)));
    g_Dh[row] = __float2half_rn(d);
    float T = sv + dmax;
    float m = fmaxf(T, 0.2f * T);
    g_Ph[row] = __float2half_rn(__expf(T - m));
    g_Rh[row] = __float2half_rn(__expf(0.2f * T - m));
    g_Th[row] = __float2half_rn(-sv);
}

// ================== attention: KT=64 stages, triple buffer, 1 sync/stage ==================
#define VBUF (128 * VSTR * 2)                          // 18432 B
#define A_SMEM (3 * VBUF + 6144 + 1024)

__global__ __launch_bounds__(256) void attn_mma_kernel(float* __restrict__ out) {
    extern __shared__ __align__(16) char adyn[];
    __half* Dsh = (__half*)(adyn + 3 * VBUF);
    __half* Qsh = Dsh + Nn;
    __half* Ssh = Qsh + Nn;
    __half* Pn = Ssh + Nn;
    __half* Rn = Pn + 128;
    __half* Tn = Rn + 128;

    int tid = threadIdx.x;
    int warp = tid >> 5, lane = tid & 31;
    int warp_m = warp & 3, warp_n = warp >> 2;
    int bh = blockIdx.z, b = bh >> 2, h = bh & 3;
    int i0 = blockIdx.x * 128, u0 = blockIdx.y * 128;

    for (int j = tid; j < Nn; j += 256) {
        Dsh[j] = g_Dh[bh * Nn + j];
        Qsh[j] = g_Qh[bh * Nn + j];
        Ssh[j] = g_Sh[bh * Nn + j];
    }
    if (tid < 128) {
        Pn[tid] = g_Ph[bh * Nn + i0 + tid];
        Rn[tid] = g_Rh[bh * Nn + i0 + tid];
        Tn[tid] = g_Th[bh * Nn + i0 + tid];
    }

    int row = tid >> 1, seg = tid & 1;                 // 128 rows x 2 segs of 64B
    uint32_t vt0 = (uint32_t)__cvta_generic_to_shared(adyn);

    auto issue = [&](int st, int bufi) {
        int j0 = st * 64;
        uint32_t d = vt0 + bufi * VBUF + row * (VSTR * 2) + seg * 64;
        const __half* g = g_vt + ((size_t)bh * Uu + u0 + row) * Nn + j0 + seg * 32;
        cp16(d, g);          cp16(d + 16, g + 8);
        cp16(d + 32, g + 16); cp16(d + 48, g + 24);
    };

    float acc[2][8][4];
#pragma unroll
    for (int mt = 0; mt < 2; mt++)
#pragma unroll
        for (int nt = 0; nt < 8; nt++)
#pragma unroll
            for (int q = 0; q < 4; q++) acc[mt][nt][q] = 0.f;
    float rs[4] = {0.f, 0.f, 0.f, 0.f};

    issue(0, 0); cp_commit();
    issue(1, 1); cp_commit();
    __syncthreads();                                   // Dsh/Qsh/Ssh/Pn visible

    __half2 Pv[4], Rv[4], Tv[4];
#pragma unroll
    for (int q = 0; q < 4; q++) {
        int r = warp_m * 32 + (q >> 1) * 16 + (q & 1) * 8 + (lane >> 2);
        Pv[q] = __half2half2(Pn[r]);
        Rv[q] = __half2half2(Rn[r]);
        Tv[q] = __half2half2(Tn[r]);
    }

    uint32_t b_off = (uint32_t)(warp_n * 64 + (lane & 7)) * (VSTR * 2) + ((lane >> 3) * 8) * 2;

    for (int st = 0; st < 16; st++) {
        if (st < 15) cp_wait<1>(); else cp_wait<0>();
        __syncthreads();                               // stage st ready; stage st-1 compute done everywhere
        if (st + 2 < 16) { issue(st + 2, (st + 2) % 3); cp_commit(); }

        uint32_t bb = vt0 + (st % 3) * VBUF;

#pragma unroll
        for (int kp = 0; kp < 2; kp++) {               // two k32 halves of the 64-wide stage
            uint32_t bfr[8][4];
#pragma unroll
            for (int nt = 0; nt < 8; nt++)
                ldm_x4(bfr[nt], bb + b_off + nt * 8 * (VSTR * 2) + kp * 64);

#pragma unroll
            for (int kk = 0; kk < 2; kk++) {
                int c = st * 64 + kp * 32 + kk * 16 + (lane & 3) * 2;
                __half2 Qa = *(const __half2*)&Qsh[c], Qb = *(const __half2*)&Qsh[c + 8];
                __half2 Sa = *(const __half2*)&Ssh[c], Sb = *(const __half2*)&Ssh[c + 8];
                __half2 Da = *(const __half2*)&Dsh[c], Db = *(const __half2*)&Dsh[c + 8];

                uint32_t aW[2][4];
#pragma unroll
                for (int mt = 0; mt < 2; mt++) {
#pragma unroll
                    for (int dq = 0; dq < 2; dq++) {
                        int q = mt * 2 + dq;
                        __half2 mA = __hge2(Da, Tv[q]);
                        __half2 wPa = __hmul2(Pv[q], Qa);
                        __half2 wRa = __hmul2(Rv[q], Sa);
                        __half2 wa = __hfma2(__hsub2(wPa, wRa), mA, wRa);
                        __half2 mB = __hge2(Db, Tv[q]);
                        __half2 wPb = __hmul2(Pv[q], Qb);
                        __half2 wRb = __hmul2(Rv[q], Sb);
                        __half2 wb = __hfma2(__hsub2(wPb, wRb), mB, wRb);
                        aW[mt][dq]     = *reinterpret_cast<uint32_t*>(&wa);
                        aW[mt][dq + 2] = *reinterpret_cast<uint32_t*>(&wb);
                        __half2 hsum = __hadd2(wa, wb);
                        float2 f = __half22float2(hsum);
                        rs[q] += f.x + f.y;
                    }
                }
#pragma unroll
                for (int nt = 0; nt < 8; nt++)
#pragma unroll
                    for (int mt = 0; mt < 2; mt++)
                        mma16816(acc[mt][nt], aW[mt], bfr[nt][2 * kk], bfr[nt][2 * kk + 1]);
            }
        }
    }

#pragma unroll
    for (int q = 0; q < 4; q++) {
        rs[q] += __shfl_xor_sync(0xffffffffu, rs[q], 1);
        rs[q] += __shfl_xor_sync(0xffffffffu, rs[q], 2);
        rs[q] = 1.0f / rs[q];
    }

#pragma unroll
    for (int mt = 0; mt < 2; mt++) {
        int i_lo = i0 + warp_m * 32 + mt * 16 + (lane >> 2);
        float inv0 = rs[mt * 2], inv1 = rs[mt * 2 + 1];
#pragma unroll
        for (int nt = 0; nt < 8; nt++) {
            int u = u0 + warp_n * 64 + nt * 8 + (lane & 3) * 2;
            size_t o0 = ((size_t)(b * Nn + i_lo)) * (Hh * Uu) + h * Uu + u;
            size_t o1 = ((size_t)(b * Nn + i_lo + 8)) * (Hh * Uu) + h * Uu + u;
            *(float2*)&out[o0] = make_float2(acc[mt][nt][0] * inv0, acc[mt][nt][1] * inv0);
            *(float2*)&out[o1] = make_float2(acc[mt][nt][2] * inv1, acc[mt][nt][3] * inv1);
        }
    }
}

// ---------------------------------------------------------------------------
extern "C" void kernel_launch(void* const* d_in, const int* in_sizes, int n_in,
                              void* d_out, int out_size) {
    (void)in_sizes; (void)n_in; (void)out_size;
    const float* x     = (const float*)d_in[0];
    const float* W     = (const float*)d_in[1];
    const float* a_src = (const float*)d_in[2];
    const float* a_dst = (const float*)d_in[3];
    float* out = (float*)d_out;

    cudaFuncSetAttribute(proj_mma_kernel, cudaFuncAttributeMaxDynamicSharedMemorySize, P_SMEM);
    cudaFuncSetAttribute(attn_mma_kernel, cudaFuncAttributeMaxDynamicSharedMemorySize, A_SMEM);

    prep_x_kernel<<<(Bb * Nn * Ff) / 1024, 256>>>(x);
    prep_wt_kernel<<<(Hh * Uu * Ff) / 256, 256>>>(W);
    proj_mma_kernel<<<dim3(8, 2, BHt), 256, P_SMEM>>>(a_src, a_dst);
    prep_pqrs_kernel<<<BHt, 1024>>>();
    attn_mma_kernel<<<dim3(8, 2, BHt), 256, A_SMEM>>>(out);
}

// round 14
// speedup vs baseline: 1.1111x; 1.0710x over previous
#include <cuda_runtime.h>
#include <cuda_fp16.h>
#include <cstdint>

#define Bb 8
#define Nn 1024
#define Ff 256
#define Hh 4
#define Uu 256
#define BHt (Bb * Hh)

#define STRIDE 40    // proj smem row stride in halves (80B)
#define VSTR 72      // attn V row stride in halves (144B)

// ---------------- device scratch (static, no allocation) ----------------
__device__ __half g_xh[(size_t)Bb * Nn * Ff];       // x fp16 [b][n][f]
__device__ __half g_vt[(size_t)BHt * Uu * Nn];      // h^T fp16 [bh][u][n]
__device__ __half g_wt[Hh * Uu * Ff];               // W^T fp16 [h][u][f]
__device__ float g_wa_src[Hh * Ff];                 // (W @ a_src)[h][f] fp32
__device__ float g_wa_dst[Hh * Ff];
__device__ float g_src[BHt * Nn];                   // exact fp32 logits
__device__ float g_dst[BHt * Nn];
__device__ __half g_Qh[BHt * Nn];
__device__ __half g_Sh[BHt * Nn];
__device__ __half g_Dh[BHt * Nn];
__device__ __half g_Ph[BHt * Nn];
__device__ __half g_Rh[BHt * Nn];
__device__ __half g_Th[BHt * Nn];

// ---------------- PTX helpers ----------------
__device__ __forceinline__ void mma16816(float* c, const uint32_t* a, uint32_t b0, uint32_t b1) {
    asm volatile(
        "mma.sync.aligned.m16n8k16.row.col.f32.f16.f16.f32 "
        "{%0,%1,%2,%3}, {%4,%5,%6,%7}, {%8,%9}, {%0,%1,%2,%3};"
        : "+f"(c[0]), "+f"(c[1]), "+f"(c[2]), "+f"(c[3])
        : "r"(a[0]), "r"(a[1]), "r"(a[2]), "r"(a[3]), "r"(b0), "r"(b1));
}
__device__ __forceinline__ void ldm_x4(uint32_t* r, uint32_t addr) {
    asm volatile("ldmatrix.sync.aligned.m8n8.x4.shared.b16 {%0,%1,%2,%3}, [%4];"
                 : "=r"(r[0]), "=r"(r[1]), "=r"(r[2]), "=r"(r[3]) : "r"(addr));
}
__device__ __forceinline__ void cp16(uint32_t dst, const void* src) {
    asm volatile("cp.async.ca.shared.global [%0], [%1], 16;" :: "r"(dst), "l"(src));
}
__device__ __forceinline__ void cp_commit() { asm volatile("cp.async.commit_group;"); }
template <int N> __device__ __forceinline__ void cp_wait() {
    asm volatile("cp.async.wait_group %0;" :: "n"(N));
}

// ================== prep: x -> fp16 ==================
__global__ __launch_bounds__(256) void prep_x_kernel(const float* __restrict__ x) {
    int idx = blockIdx.x * 256 + threadIdx.x;          // float4 index
    float4 v = ((const float4*)x)[idx];
    __half2 hi01 = __floats2half2_rn(v.x, v.y);
    __half2 hi23 = __floats2half2_rn(v.z, v.w);
    ((__half2*)g_xh)[idx * 2] = hi01;
    ((__half2*)g_xh)[idx * 2 + 1] = hi23;
}

// ================== prep: W^T fp16 [h][u][f] ==================
__global__ __launch_bounds__(256) void prep_wt_kernel(const float* __restrict__ W) {
    int idx = blockIdx.x * 256 + threadIdx.x;
    int f = idx & 255, u = (idx >> 8) & 255, h = idx >> 16;
    float w = W[((size_t)(h * 256 + f)) * 256 + u];
    g_wt[((size_t)(h * 256 + u)) * 256 + f] = __float2half_rn(w);
}

// ================== prep: Wa[h][f] = sum_u W[h,f,u] * a[h,u]  (fp32 exact) ==================
__global__ __launch_bounds__(128) void prep_wa_kernel(const float* __restrict__ W,
                                                      const float* __restrict__ a_src,
                                                      const float* __restrict__ a_dst) {
    int warp = threadIdx.x >> 5, lane = threadIdx.x & 31;
    int rowid = blockIdx.x * 4 + warp;                 // [0, H*F)
    int h = rowid >> 8, f = rowid & 255;
    const float* wrow = W + ((size_t)(h * 256 + f)) * 256;
    const float* as = a_src + h * 256;
    const float* ad = a_dst + h * 256;
    float s1 = 0.f, s2 = 0.f;
#pragma unroll
    for (int u = lane * 4; u < 256; u += 128) {
        float4 w = *(const float4*)&wrow[u];
        float4 p = *(const float4*)&as[u];
        float4 q = *(const float4*)&ad[u];
        s1 += w.x * p.x + w.y * p.y + w.z * p.z + w.w * p.w;
        s2 += w.x * q.x + w.y * q.y + w.z * q.z + w.w * q.w;
    }
#pragma unroll
    for (int o = 16; o > 0; o >>= 1) {
        s1 += __shfl_down_sync(0xffffffffu, s1, o);
        s2 += __shfl_down_sync(0xffffffffu, s2, o);
    }
    if (lane == 0) { g_wa_src[rowid] = s1; g_wa_dst[rowid] = s2; }
}

// ================== src/dst: exact fp32 GEMV from x (one warp per (b,n)) ==================
__global__ __launch_bounds__(256) void srcdst_kernel(const float* __restrict__ x) {
    int warp = threadIdx.x >> 5, lane = threadIdx.x & 31;
    int row = blockIdx.x * 8 + warp;                   // [0, B*N)
    int b = row >> 10, n = row & 1023;
    const float* xr = x + (size_t)row * Ff;

    float xv[8];
    float4 v0 = *(const float4*)&xr[lane * 4];
    float4 v1 = *(const float4*)&xr[128 + lane * 4];
    xv[0] = v0.x; xv[1] = v0.y; xv[2] = v0.z; xv[3] = v0.w;
    xv[4] = v1.x; xv[5] = v1.y; xv[6] = v1.z; xv[7] = v1.w;

#pragma unroll
    for (int h = 0; h < Hh; h++) {
        const float* ws = g_wa_src + h * Ff;
        const float* wd = g_wa_dst + h * Ff;
        float s1 = 0.f, s2 = 0.f;
        float4 p0 = *(const float4*)&ws[lane * 4];
        float4 p1 = *(const float4*)&ws[128 + lane * 4];
        float4 q0 = *(const float4*)&wd[lane * 4];
        float4 q1 = *(const float4*)&wd[128 + lane * 4];
        s1 = xv[0]*p0.x + xv[1]*p0.y + xv[2]*p0.z + xv[3]*p0.w
           + xv[4]*p1.x + xv[5]*p1.y + xv[6]*p1.z + xv[7]*p1.w;
        s2 = xv[0]*q0.x + xv[1]*q0.y + xv[2]*q0.z + xv[3]*q0.w
           + xv[4]*q1.x + xv[5]*q1.y + xv[6]*q1.z + xv[7]*q1.w;
#pragma unroll
        for (int o = 16; o > 0; o >>= 1) {
            s1 += __shfl_down_sync(0xffffffffu, s1, o);
            s2 += __shfl_down_sync(0xffffffffu, s2, o);
        }
        if (lane == 0) {
            int bh = b * Hh + h;
            g_src[bh * Nn + n] = s1;
            g_dst[bh * Nn + n] = s2;
        }
    }
}

// ================== proj: h = xh @ WT  — SINGLE fp16 term ==================
#define PBUF (2 * 128 * STRIDE * 2)                    // 20480 B per buffer
#define P_SMEM (2 * PBUF)

__global__ __launch_bounds__(256) void proj_mma_kernel() {
    extern __shared__ __align__(16) char dyn[];

    int tid = threadIdx.x;
    int warp = tid >> 5, lane = tid & 31;
    int warp_m = warp & 3, warp_n = warp >> 2;
    int bh = blockIdx.z, b = bh >> 2, h = bh & 3;
    int i0 = blockIdx.x * 128, u0 = blockIdx.y * 128;

    uint32_t smb = (uint32_t)__cvta_generic_to_shared(dyn);
    int row = tid >> 1, seg = tid & 1;

    auto issue = [&](int st, int bufi) {
        int f0 = st * 32;
        uint32_t base = smb + bufi * PBUF + row * (STRIDE * 2) + seg * 32;
        const __half* gA = g_xh + ((size_t)(b * Nn + i0 + row)) * Ff + f0 + seg * 16;
        const __half* gW = g_wt + ((size_t)(h * 256 + u0 + row)) * 256 + f0 + seg * 16;
        cp16(base, gA);          cp16(base + 16, gA + 8);
        cp16(base + 10240, gW);  cp16(base + 10240 + 16, gW + 8);
    };

    float acc[2][8][4];
#pragma unroll
    for (int mt = 0; mt < 2; mt++)
#pragma unroll
        for (int nt = 0; nt < 8; nt++)
#pragma unroll
            for (int q = 0; q < 4; q++) acc[mt][nt][q] = 0.f;

    issue(0, 0);
    cp_commit();

    uint32_t a_off = (uint32_t)(warp_m * 32 + (lane & 15)) * (STRIDE * 2) + ((lane >> 4) * 8) * 2;
    uint32_t b_off = (uint32_t)(warp_n * 64 + (lane & 7)) * (STRIDE * 2) + ((lane >> 3) * 8) * 2;

    for (int st = 0; st < 8; st++) {
        if (st < 7) { issue(st + 1, (st + 1) & 1); cp_commit(); cp_wait<1>(); }
        else cp_wait<0>();
        __syncthreads();

        uint32_t bb = smb + (st & 1) * PBUF;
        uint32_t aH[2][2][4];
#pragma unroll
        for (int mt = 0; mt < 2; mt++)
#pragma unroll
            for (int kk = 0; kk < 2; kk++)
                ldm_x4(aH[mt][kk], bb + a_off + mt * 16 * (STRIDE * 2) + kk * 32);
#pragma unroll
        for (int nt = 0; nt < 8; nt++) {
            uint32_t bH[4];
            ldm_x4(bH, bb + 10240 + b_off + nt * 8 * (STRIDE * 2));
#pragma unroll
            for (int kk = 0; kk < 2; kk++)
#pragma unroll
                for (int mt = 0; mt < 2; mt++)
                    mma16816(acc[mt][nt], aH[mt][kk], bH[2 * kk], bH[2 * kk + 1]);
        }
        __syncthreads();
    }

    // ---- epilogue: fp16 transpose restage -> g_vt [u][n] ----
    __half (*tr)[136] = (__half (*)[136])dyn;
#pragma unroll
    for (int mt = 0; mt < 2; mt++) {
        int i_loc = warp_m * 32 + mt * 16 + (lane >> 2);
#pragma unroll
        for (int nt = 0; nt < 8; nt++) {
            int u_loc = warp_n * 64 + nt * 8 + (lane & 3) * 2;
            tr[u_loc][i_loc]         = __float2half_rn(acc[mt][nt][0]);
            tr[u_loc + 1][i_loc]     = __float2half_rn(acc[mt][nt][1]);
            tr[u_loc][i_loc + 8]     = __float2half_rn(acc[mt][nt][2]);
            tr[u_loc + 1][i_loc + 8] = __float2half_rn(acc[mt][nt][3]);
        }
    }
    __syncthreads();
    {
        const float4* srcp = (const float4*)&tr[row][seg * 64];
        float4* dstp = (float4*)&g_vt[((size_t)bh * Uu + u0 + row) * Nn + i0 + seg * 64];
#pragma unroll
        for (int k = 0; k < 8; k++) dstp[k] = srcp[k];
    }
}

// ================== prep: P/Q/R/S/D/thr fp16 per (b,h) from exact logits ==================
__global__ __launch_bounds__(1024) void prep_pqrs_kernel() {
    __shared__ float red[1024];
    int bh = blockIdx.x, tid = threadIdx.x;
    int row = bh * Nn + tid;
    float d = g_dst[row];
    float sv = g_src[row];
    red[tid] = d;
    __syncthreads();
    for (int s = 512; s > 0; s >>= 1) {
        if (tid < s) red[tid] = fmaxf(red[tid], red[tid + s]);
        __syncthreads();
    }
    float dmax = red[0];
    g_Qh[row] = __float2half_rn(__expf(d - dmax));
    g_Sh[row] = __float2half_rn(__expf(0.2f * (d - dmax)));
    g_Dh[row] = __float2half_rn(d);
    float T = sv + dmax;
    float m = fmaxf(T, 0.2f * T);
    g_Ph[row] = __float2half_rn(__expf(T - m));
    g_Rh[row] = __float2half_rn(__expf(0.2f * T - m));
    g_Th[row] = __float2half_rn(-sv);
}

// ================== attention (R13, unchanged): KT=64, triple buffer ==================
#define VBUF (128 * VSTR * 2)                          // 18432 B
#define A_SMEM (3 * VBUF + 6144 + 1024)

__global__ __launch_bounds__(256) void attn_mma_kernel(float* __restrict__ out) {
    extern __shared__ __align__(16) char adyn[];
    __half* Dsh = (__half*)(adyn + 3 * VBUF);
    __half* Qsh = Dsh + Nn;
    __half* Ssh = Qsh + Nn;
    __half* Pn = Ssh + Nn;
    __half* Rn = Pn + 128;
    __half* Tn = Rn + 128;

    int tid = threadIdx.x;
    int warp = tid >> 5, lane = tid & 31;
    int warp_m = warp & 3, warp_n = warp >> 2;
    int bh = blockIdx.z, b = bh >> 2, h = bh & 3;
    int i0 = blockIdx.x * 128, u0 = blockIdx.y * 128;

    for (int j = tid; j < Nn; j += 256) {
        Dsh[j] = g_Dh[bh * Nn + j];
        Qsh[j] = g_Qh[bh * Nn + j];
        Ssh[j] = g_Sh[bh * Nn + j];
    }
    if (tid < 128) {
        Pn[tid] = g_Ph[bh * Nn + i0 + tid];
        Rn[tid] = g_Rh[bh * Nn + i0 + tid];
        Tn[tid] = g_Th[bh * Nn + i0 + tid];
    }

    int row = tid >> 1, seg = tid & 1;
    uint32_t vt0 = (uint32_t)__cvta_generic_to_shared(adyn);

    auto issue = [&](int st, int bufi) {
        int j0 = st * 64;
        uint32_t d = vt0 + bufi * VBUF + row * (VSTR * 2) + seg * 64;
        const __half* g = g_vt + ((size_t)bh * Uu + u0 + row) * Nn + j0 + seg * 32;
        cp16(d, g);           cp16(d + 16, g + 8);
        cp16(d + 32, g + 16); cp16(d + 48, g + 24);
    };

    float acc[2][8][4];
#pragma unroll
    for (int mt = 0; mt < 2; mt++)
#pragma unroll
        for (int nt = 0; nt < 8; nt++)
#pragma unroll
            for (int q = 0; q < 4; q++) acc[mt][nt][q] = 0.f;
    float rs[4] = {0.f, 0.f, 0.f, 0.f};

    issue(0, 0); cp_commit();
    issue(1, 1); cp_commit();
    __syncthreads();

    __half2 Pv[4], Rv[4], Tv[4];
#pragma unroll
    for (int q = 0; q < 4; q++) {
        int r = warp_m * 32 + (q >> 1) * 16 + (q & 1) * 8 + (lane >> 2);
        Pv[q] = __half2half2(Pn[r]);
        Rv[q] = __half2half2(Rn[r]);
        Tv[q] = __half2half2(Tn[r]);
    }

    uint32_t b_off = (uint32_t)(warp_n * 64 + (lane & 7)) * (VSTR * 2) + ((lane >> 3) * 8) * 2;

    for (int st = 0; st < 16; st++) {
        if (st < 15) cp_wait<1>(); else cp_wait<0>();
        __syncthreads();
        if (st + 2 < 16) { issue(st + 2, (st + 2) % 3); cp_commit(); }

        uint32_t bb = vt0 + (st % 3) * VBUF;

#pragma unroll
        for (int kp = 0; kp < 2; kp++) {
            uint32_t bfr[8][4];
#pragma unroll
            for (int nt = 0; nt < 8; nt++)
                ldm_x4(bfr[nt], bb + b_off + nt * 8 * (VSTR * 2) + kp * 64);

#pragma unroll
            for (int kk = 0; kk < 2; kk++) {
                int c = st * 64 + kp * 32 + kk * 16 + (lane & 3) * 2;
                __half2 Qa = *(const __half2*)&Qsh[c], Qb = *(const __half2*)&Qsh[c + 8];
                __half2 Sa = *(const __half2*)&Ssh[c], Sb = *(const __half2*)&Ssh[c + 8];
                __half2 Da = *(const __half2*)&Dsh[c], Db = *(const __half2*)&Dsh[c + 8];

                uint32_t aW[2][4];
#pragma unroll
                for (int mt = 0; mt < 2; mt++) {
#pragma unroll
                    for (int dq = 0; dq < 2; dq++) {
                        int q = mt * 2 + dq;
                        __half2 mA = __hge2(Da, Tv[q]);
                        __half2 wPa = __hmul2(Pv[q], Qa);
                        __half2 wRa = __hmul2(Rv[q], Sa);
                        __half2 wa = __hfma2(__hsub2(wPa, wRa), mA, wRa);
                        __half2 mB = __hge2(Db, Tv[q]);
                        __half2 wPb = __hmul2(Pv[q], Qb);
                        __half2 wRb = __hmul2(Rv[q], Sb);
                        __half2 wb = __hfma2(__hsub2(wPb, wRb), mB, wRb);
                        aW[mt][dq]     = *reinterpret_cast<uint32_t*>(&wa);
                        aW[mt][dq + 2] = *reinterpret_cast<uint32_t*>(&wb);
                        __half2 hsum = __hadd2(wa, wb);
                        float2 f = __half22float2(hsum);
                        rs[q] += f.x + f.y;
                    }
                }
#pragma unroll
                for (int nt = 0; nt < 8; nt++)
#pragma unroll
                    for (int mt = 0; mt < 2; mt++)
                        mma16816(acc[mt][nt], aW[mt], bfr[nt][2 * kk], bfr[nt][2 * kk + 1]);
            }
        }
    }

#pragma unroll
    for (int q = 0; q < 4; q++) {
        rs[q] += __shfl_xor_sync(0xffffffffu, rs[q], 1);
        rs[q] += __shfl_xor_sync(0xffffffffu, rs[q], 2);
        rs[q] = 1.0f / rs[q];
    }

#pragma unroll
    for (int mt = 0; mt < 2; mt++) {
        int i_lo = i0 + warp_m * 32 + mt * 16 + (lane >> 2);
        float inv0 = rs[mt * 2], inv1 = rs[mt * 2 + 1];
#pragma unroll
        for (int nt = 0; nt < 8; nt++) {
            int u = u0 + warp_n * 64 + nt * 8 + (lane & 3) * 2;
            size_t o0 = ((size_t)(b * Nn + i_lo)) * (Hh * Uu) + h * Uu + u;
            size_t o1 = ((size_t)(b * Nn + i_lo + 8)) * (Hh * Uu) + h * Uu + u;
            *(float2*)&out[o0] = make_float2(acc[mt][nt][0] * inv0, acc[mt][nt][1] * inv0);
            *(float2*)&out[o1] = make_float2(acc[mt][nt][2] * inv1, acc[mt][nt][3] * inv1);
        }
    }
}

// ---------------------------------------------------------------------------
extern "C" void kernel_launch(void* const* d_in, const int* in_sizes, int n_in,
                              void* d_out, int out_size) {
    (void)in_sizes; (void)n_in; (void)out_size;
    const float* x     = (const float*)d_in[0];
    const float* W     = (const float*)d_in[1];
    const float* a_src = (const float*)d_in[2];
    const float* a_dst = (const float*)d_in[3];
    float* out = (float*)d_out;

    cudaFuncSetAttribute(proj_mma_kernel, cudaFuncAttributeMaxDynamicSharedMemorySize, P_SMEM);
    cudaFuncSetAttribute(attn_mma_kernel, cudaFuncAttributeMaxDynamicSharedMemorySize, A_SMEM);

    prep_x_kernel<<<(Bb * Nn * Ff) / 1024, 256>>>(x);
    prep_wt_kernel<<<(Hh * Uu * Ff) / 256, 256>>>(W);
    prep_wa_kernel<<<(Hh * Ff) / 4, 128>>>(W, a_src, a_dst);
    srcdst_kernel<<<(Bb * Nn) / 8, 256>>>(x);
    prep_pqrs_kernel<<<BHt, 1024>>>();
    proj_mma_kernel<<<dim3(8, 2, BHt), 256, P_SMEM>>>();
    attn_mma_kernel<<<dim3(8, 2, BHt), 256, A_SMEM>>>(out);
}

// round 15
// speedup vs baseline: 1.1426x; 1.0283x over previous
#include <cuda_runtime.h>
#include <cuda_fp16.h>
#include <cstdint>

#define Bb 8
#define Nn 1024
#define Ff 256
#define Hh 4
#define Uu 256
#define BHt (Bb * Hh)

#define STRIDE 40    // proj smem row stride in halves (80B)
#define VSTR 72      // attn V row stride in halves (144B)

// ---------------- device scratch (static, no allocation) ----------------
__device__ __half g_xh[(size_t)Bb * Nn * Ff];       // x fp16 [b][n][f]
__device__ __half g_vt[(size_t)BHt * Uu * Nn];      // h^T fp16 [bh][u][n]
__device__ __half g_wt[Hh * Uu * Ff];               // W^T fp16 [h][u][f]
__device__ float g_wa_src[Hh * Ff];                 // (W @ a_src)[h][f] fp32
__device__ float g_wa_dst[Hh * Ff];
__device__ float g_src[BHt * Nn];                   // exact fp32 logits
__device__ float g_dst[BHt * Nn];
__device__ __half g_Qh[BHt * Nn];
__device__ __half g_Sh[BHt * Nn];
__device__ __half g_Dh[BHt * Nn];
__device__ __half g_Ph[BHt * Nn];
__device__ __half g_Rh[BHt * Nn];
__device__ __half g_Th[BHt * Nn];

// ---------------- PTX helpers ----------------
__device__ __forceinline__ void mma16816(float* c, const uint32_t* a, uint32_t b0, uint32_t b1) {
    asm volatile(
        "mma.sync.aligned.m16n8k16.row.col.f32.f16.f16.f32 "
        "{%0,%1,%2,%3}, {%4,%5,%6,%7}, {%8,%9}, {%0,%1,%2,%3};"
        : "+f"(c[0]), "+f"(c[1]), "+f"(c[2]), "+f"(c[3])
        : "r"(a[0]), "r"(a[1]), "r"(a[2]), "r"(a[3]), "r"(b0), "r"(b1));
}
__device__ __forceinline__ void ldm_x4(uint32_t* r, uint32_t addr) {
    asm volatile("ldmatrix.sync.aligned.m8n8.x4.shared.b16 {%0,%1,%2,%3}, [%4];"
                 : "=r"(r[0]), "=r"(r[1]), "=r"(r[2]), "=r"(r[3]) : "r"(addr));
}
__device__ __forceinline__ void cp16(uint32_t dst, const void* src) {
    asm volatile("cp.async.ca.shared.global [%0], [%1], 16;" :: "r"(dst), "l"(src));
}
__device__ __forceinline__ void cp_commit() { asm volatile("cp.async.commit_group;"); }
template <int N> __device__ __forceinline__ void cp_wait() {
    asm volatile("cp.async.wait_group %0;" :: "n"(N));
}

// ================== fused prep: x->fp16 | W^T fp16 | Wa fp32 ==================
// blocks [0, 2048)          : x convert (one float4 per thread)
// blocks [2048, 3072)       : W^T convert
// blocks [3072, 3200)       : Wa GEMV (8 warps per block, warp-per-(h,f) row)
#define PX_BLOCKS 2048
#define PW_BLOCKS 1024
#define PA_BLOCKS 128

__global__ __launch_bounds__(256) void prep_all_kernel(const float* __restrict__ x,
                                                       const float* __restrict__ W,
                                                       const float* __restrict__ a_src,
                                                       const float* __restrict__ a_dst) {
    int blk = blockIdx.x;
    if (blk < PX_BLOCKS) {
        int idx = blk * 256 + threadIdx.x;
        float4 v = ((const float4*)x)[idx];
        ((__half2*)g_xh)[idx * 2]     = __floats2half2_rn(v.x, v.y);
        ((__half2*)g_xh)[idx * 2 + 1] = __floats2half2_rn(v.z, v.w);
    } else if (blk < PX_BLOCKS + PW_BLOCKS) {
        int idx = (blk - PX_BLOCKS) * 256 + threadIdx.x;
        int f = idx & 255, u = (idx >> 8) & 255, h = idx >> 16;
        float w = W[((size_t)(h * 256 + f)) * 256 + u];
        g_wt[((size_t)(h * 256 + u)) * 256 + f] = __float2half_rn(w);
    } else {
        int warp = threadIdx.x >> 5, lane = threadIdx.x & 31;
        int rowid = (blk - PX_BLOCKS - PW_BLOCKS) * 8 + warp;   // [0, H*F)
        int h = rowid >> 8;
        const float* wrow = W + (size_t)rowid * 256;
        const float* as = a_src + h * 256;
        const float* ad = a_dst + h * 256;
        float s1 = 0.f, s2 = 0.f;
#pragma unroll
        for (int u = lane * 4; u < 256; u += 128) {
            float4 w = *(const float4*)&wrow[u];
            float4 p = *(const float4*)&as[u];
            float4 q = *(const float4*)&ad[u];
            s1 += w.x * p.x + w.y * p.y + w.z * p.z + w.w * p.w;
            s2 += w.x * q.x + w.y * q.y + w.z * q.z + w.w * q.w;
        }
#pragma unroll
        for (int o = 16; o > 0; o >>= 1) {
            s1 += __shfl_down_sync(0xffffffffu, s1, o);
            s2 += __shfl_down_sync(0xffffffffu, s2, o);
        }
        if (lane == 0) { g_wa_src[rowid] = s1; g_wa_dst[rowid] = s2; }
    }
}

// ================== src/dst: exact fp32 GEMV from x, Wa staged in smem ==================
__global__ __launch_bounds__(256) void srcdst_kernel(const float* __restrict__ x) {
    __shared__ float sWs[Hh * Ff];   // 4 KB
    __shared__ float sWd[Hh * Ff];   // 4 KB
    int tid = threadIdx.x;
#pragma unroll
    for (int k = 0; k < 4; k++) {
        sWs[tid + k * 256] = g_wa_src[tid + k * 256];
        sWd[tid + k * 256] = g_wa_dst[tid + k * 256];
    }
    __syncthreads();

    int warp = tid >> 5, lane = tid & 31;
    int row = blockIdx.x * 8 + warp;                   // [0, B*N)
    int b = row >> 10, n = row & 1023;
    const float* xr = x + (size_t)row * Ff;

    float xv[8];
    float4 v0 = *(const float4*)&xr[lane * 4];
    float4 v1 = *(const float4*)&xr[128 + lane * 4];
    xv[0] = v0.x; xv[1] = v0.y; xv[2] = v0.z; xv[3] = v0.w;
    xv[4] = v1.x; xv[5] = v1.y; xv[6] = v1.z; xv[7] = v1.w;

#pragma unroll
    for (int h = 0; h < Hh; h++) {
        const float* ws = sWs + h * Ff;
        const float* wd = sWd + h * Ff;
        float4 p0 = *(const float4*)&ws[lane * 4];
        float4 p1 = *(const float4*)&ws[128 + lane * 4];
        float4 q0 = *(const float4*)&wd[lane * 4];
        float4 q1 = *(const float4*)&wd[128 + lane * 4];
        float s1 = xv[0]*p0.x + xv[1]*p0.y + xv[2]*p0.z + xv[3]*p0.w
                 + xv[4]*p1.x + xv[5]*p1.y + xv[6]*p1.z + xv[7]*p1.w;
        float s2 = xv[0]*q0.x + xv[1]*q0.y + xv[2]*q0.z + xv[3]*q0.w
                 + xv[4]*q1.x + xv[5]*q1.y + xv[6]*q1.z + xv[7]*q1.w;
#pragma unroll
        for (int o = 16; o > 0; o >>= 1) {
            s1 += __shfl_down_sync(0xffffffffu, s1, o);
            s2 += __shfl_down_sync(0xffffffffu, s2, o);
        }
        if (lane == 0) {
            int bh = b * Hh + h;
            g_src[bh * Nn + n] = s1;
            g_dst[bh * Nn + n] = s2;
        }
    }
}

// ================== proj: h = xh @ WT — single fp16 term (R14, unchanged) ==================
#define PBUF (2 * 128 * STRIDE * 2)                    // 20480 B per buffer
#define P_SMEM (2 * PBUF)

__global__ __launch_bounds__(256) void proj_mma_kernel() {
    extern __shared__ __align__(16) char dyn[];

    int tid = threadIdx.x;
    int warp = tid >> 5, lane = tid & 31;
    int warp_m = warp & 3, warp_n = warp >> 2;
    int bh = blockIdx.z, b = bh >> 2, h = bh & 3;
    int i0 = blockIdx.x * 128, u0 = blockIdx.y * 128;

    uint32_t smb = (uint32_t)__cvta_generic_to_shared(dyn);
    int row = tid >> 1, seg = tid & 1;

    auto issue = [&](int st, int bufi) {
        int f0 = st * 32;
        uint32_t base = smb + bufi * PBUF + row * (STRIDE * 2) + seg * 32;
        const __half* gA = g_xh + ((size_t)(b * Nn + i0 + row)) * Ff + f0 + seg * 16;
        const __half* gW = g_wt + ((size_t)(h * 256 + u0 + row)) * 256 + f0 + seg * 16;
        cp16(base, gA);          cp16(base + 16, gA + 8);
        cp16(base + 10240, gW);  cp16(base + 10240 + 16, gW + 8);
    };

    float acc[2][8][4];
#pragma unroll
    for (int mt = 0; mt < 2; mt++)
#pragma unroll
        for (int nt = 0; nt < 8; nt++)
#pragma unroll
            for (int q = 0; q < 4; q++) acc[mt][nt][q] = 0.f;

    issue(0, 0);
    cp_commit();

    uint32_t a_off = (uint32_t)(warp_m * 32 + (lane & 15)) * (STRIDE * 2) + ((lane >> 4) * 8) * 2;
    uint32_t b_off = (uint32_t)(warp_n * 64 + (lane & 7)) * (STRIDE * 2) + ((lane >> 3) * 8) * 2;

    for (int st = 0; st < 8; st++) {
        if (st < 7) { issue(st + 1, (st + 1) & 1); cp_commit(); cp_wait<1>(); }
        else cp_wait<0>();
        __syncthreads();

        uint32_t bb = smb + (st & 1) * PBUF;
        uint32_t aH[2][2][4];
#pragma unroll
        for (int mt = 0; mt < 2; mt++)
#pragma unroll
            for (int kk = 0; kk < 2; kk++)
                ldm_x4(aH[mt][kk], bb + a_off + mt * 16 * (STRIDE * 2) + kk * 32);
#pragma unroll
        for (int nt = 0; nt < 8; nt++) {
            uint32_t bH[4];
            ldm_x4(bH, bb + 10240 + b_off + nt * 8 * (STRIDE * 2));
#pragma unroll
            for (int kk = 0; kk < 2; kk++)
#pragma unroll
                for (int mt = 0; mt < 2; mt++)
                    mma16816(acc[mt][nt], aH[mt][kk], bH[2 * kk], bH[2 * kk + 1]);
        }
        __syncthreads();
    }

    // ---- epilogue: fp16 transpose restage -> g_vt [u][n] ----
    __half (*tr)[136] = (__half (*)[136])dyn;
#pragma unroll
    for (int mt = 0; mt < 2; mt++) {
        int i_loc = warp_m * 32 + mt * 16 + (lane >> 2);
#pragma unroll
        for (int nt = 0; nt < 8; nt++) {
            int u_loc = warp_n * 64 + nt * 8 + (lane & 3) * 2;
            tr[u_loc][i_loc]         = __float2half_rn(acc[mt][nt][0]);
            tr[u_loc + 1][i_loc]     = __float2half_rn(acc[mt][nt][1]);
            tr[u_loc][i_loc + 8]     = __float2half_rn(acc[mt][nt][2]);
            tr[u_loc + 1][i_loc + 8] = __float2half_rn(acc[mt][nt][3]);
        }
    }
    __syncthreads();
    {
        const float4* srcp = (const float4*)&tr[row][seg * 64];
        float4* dstp = (float4*)&g_vt[((size_t)bh * Uu + u0 + row) * Nn + i0 + seg * 64];
#pragma unroll
        for (int k = 0; k < 8; k++) dstp[k] = srcp[k];
    }
}

// ================== prep: P/Q/R/S/D/thr fp16 per (b,h) from exact logits ==================
__global__ __launch_bounds__(1024) void prep_pqrs_kernel() {
    __shared__ float red[1024];
    int bh = blockIdx.x, tid = threadIdx.x;
    int row = bh * Nn + tid;
    float d = g_dst[row];
    float sv = g_src[row];
    red[tid] = d;
    __syncthreads();
    for (int s = 512; s > 0; s >>= 1) {
        if (tid < s) red[tid] = fmaxf(red[tid], red[tid + s]);
        __syncthreads();
    }
    float dmax = red[0];
    g_Qh[row] = __float2half_rn(__expf(d - dmax));
    g_Sh[row] = __float2half_rn(__expf(0.2f * (d - dmax)));
    g_Dh[row] = __float2half_rn(d);
    float T = sv + dmax;
    float m = fmaxf(T, 0.2f * T);
    g_Ph[row] = __float2half_rn(__expf(T - m));
    g_Rh[row] = __float2half_rn(__expf(0.2f * T - m));
    g_Th[row] = __float2half_rn(-sv);
}

// ================== attention (R13, unchanged): KT=64, triple buffer ==================
#define VBUF (128 * VSTR * 2)                          // 18432 B
#define A_SMEM (3 * VBUF + 6144 + 1024)

__global__ __launch_bounds__(256) void attn_mma_kernel(float* __restrict__ out) {
    extern __shared__ __align__(16) char adyn[];
    __half* Dsh = (__half*)(adyn + 3 * VBUF);
    __half* Qsh = Dsh + Nn;
    __half* Ssh = Qsh + Nn;
    __half* Pn = Ssh + Nn;
    __half* Rn = Pn + 128;
    __half* Tn = Rn + 128;

    int tid = threadIdx.x;
    int warp = tid >> 5, lane = tid & 31;
    int warp_m = warp & 3, warp_n = warp >> 2;
    int bh = blockIdx.z, b = bh >> 2, h = bh & 3;
    int i0 = blockIdx.x * 128, u0 = blockIdx.y * 128;

    for (int j = tid; j < Nn; j += 256) {
        Dsh[j] = g_Dh[bh * Nn + j];
        Qsh[j] = g_Qh[bh * Nn + j];
        Ssh[j] = g_Sh[bh * Nn + j];
    }
    if (tid < 128) {
        Pn[tid] = g_Ph[bh * Nn + i0 + tid];
        Rn[tid] = g_Rh[bh * Nn + i0 + tid];
        Tn[tid] = g_Th[bh * Nn + i0 + tid];
    }

    int row = tid >> 1, seg = tid & 1;
    uint32_t vt0 = (uint32_t)__cvta_generic_to_shared(adyn);

    auto issue = [&](int st, int bufi) {
        int j0 = st * 64;
        uint32_t d = vt0 + bufi * VBUF + row * (VSTR * 2) + seg * 64;
        const __half* g = g_vt + ((size_t)bh * Uu + u0 + row) * Nn + j0 + seg * 32;
        cp16(d, g);           cp16(d + 16, g + 8);
        cp16(d + 32, g + 16); cp16(d + 48, g + 24);
    };

    float acc[2][8][4];
#pragma unroll
    for (int mt = 0; mt < 2; mt++)
#pragma unroll
        for (int nt = 0; nt < 8; nt++)
#pragma unroll
            for (int q = 0; q < 4; q++) acc[mt][nt][q] = 0.f;
    float rs[4] = {0.f, 0.f, 0.f, 0.f};

    issue(0, 0); cp_commit();
    issue(1, 1); cp_commit();
    __syncthreads();

    __half2 Pv[4], Rv[4], Tv[4];
#pragma unroll
    for (int q = 0; q < 4; q++) {
        int r = warp_m * 32 + (q >> 1) * 16 + (q & 1) * 8 + (lane >> 2);
        Pv[q] = __half2half2(Pn[r]);
        Rv[q] = __half2half2(Rn[r]);
        Tv[q] = __half2half2(Tn[r]);
    }

    uint32_t b_off = (uint32_t)(warp_n * 64 + (lane & 7)) * (VSTR * 2) + ((lane >> 3) * 8) * 2;

    for (int st = 0; st < 16; st++) {
        if (st < 15) cp_wait<1>(); else cp_wait<0>();
        __syncthreads();
        if (st + 2 < 16) { issue(st + 2, (st + 2) % 3); cp_commit(); }

        uint32_t bb = vt0 + (st % 3) * VBUF;

#pragma unroll
        for (int kp = 0; kp < 2; kp++) {
            uint32_t bfr[8][4];
#pragma unroll
            for (int nt = 0; nt < 8; nt++)
                ldm_x4(bfr[nt], bb + b_off + nt * 8 * (VSTR * 2) + kp * 64);

#pragma unroll
            for (int kk = 0; kk < 2; kk++) {
                int c = st * 64 + kp * 32 + kk * 16 + (lane & 3) * 2;
                __half2 Qa = *(const __half2*)&Qsh[c], Qb = *(const __half2*)&Qsh[c + 8];
                __half2 Sa = *(const __half2*)&Ssh[c], Sb = *(const __half2*)&Ssh[c + 8];
                __half2 Da = *(const __half2*)&Dsh[c], Db = *(const __half2*)&Dsh[c + 8];

                uint32_t aW[2][4];
#pragma unroll
                for (int mt = 0; mt < 2; mt++) {
#pragma unroll
                    for (int dq = 0; dq < 2; dq++) {
                        int q = mt * 2 + dq;
                        __half2 mA = __hge2(Da, Tv[q]);
                        __half2 wPa = __hmul2(Pv[q], Qa);
                        __half2 wRa = __hmul2(Rv[q], Sa);
                        __half2 wa = __hfma2(__hsub2(wPa, wRa), mA, wRa);
                        __half2 mB = __hge2(Db, Tv[q]);
                        __half2 wPb = __hmul2(Pv[q], Qb);
                        __half2 wRb = __hmul2(Rv[q], Sb);
                        __half2 wb = __hfma2(__hsub2(wPb, wRb), mB, wRb);
                        aW[mt][dq]     = *reinterpret_cast<uint32_t*>(&wa);
                        aW[mt][dq + 2] = *reinterpret_cast<uint32_t*>(&wb);
                        __half2 hsum = __hadd2(wa, wb);
                        float2 f = __half22float2(hsum);
                        rs[q] += f.x + f.y;
                    }
                }
#pragma unroll
                for (int nt = 0; nt < 8; nt++)
#pragma unroll
                    for (int mt = 0; mt < 2; mt++)
                        mma16816(acc[mt][nt], aW[mt], bfr[nt][2 * kk], bfr[nt][2 * kk + 1]);
            }
        }
    }

#pragma unroll
    for (int q = 0; q < 4; q++) {
        rs[q] += __shfl_xor_sync(0xffffffffu, rs[q], 1);
        rs[q] += __shfl_xor_sync(0xffffffffu, rs[q], 2);
        rs[q] = 1.0f / rs[q];
    }

#pragma unroll
    for (int mt = 0; mt < 2; mt++) {
        int i_lo = i0 + warp_m * 32 + mt * 16 + (lane >> 2);
        float inv0 = rs[mt * 2], inv1 = rs[mt * 2 + 1];
#pragma unroll
        for (int nt = 0; nt < 8; nt++) {
            int u = u0 + warp_n * 64 + nt * 8 + (lane & 3) * 2;
            size_t o0 = ((size_t)(b * Nn + i_lo)) * (Hh * Uu) + h * Uu + u;
            size_t o1 = ((size_t)(b * Nn + i_lo + 8)) * (Hh * Uu) + h * Uu + u;
            *(float2*)&out[o0] = make_float2(acc[mt][nt][0] * inv0, acc[mt][nt][1] * inv0);
            *(float2*)&out[o1] = make_float2(acc[mt][nt][2] * inv1, acc[mt][nt][3] * inv1);
        }
    }
}

// ---------------------------------------------------------------------------
extern "C" void kernel_launch(void* const* d_in, const int* in_sizes, int n_in,
                              void* d_out, int out_size) {
    (void)in_sizes; (void)n_in; (void)out_size;
    const float* x     = (const float*)d_in[0];
    const float* W     = (const float*)d_in[1];
    const float* a_src = (const float*)d_in[2];
    const float* a_dst = (const float*)d_in[3];
    float* out = (float*)d_out;

    cudaFuncSetAttribute(proj_mma_kernel, cudaFuncAttributeMaxDynamicSharedMemorySize, P_SMEM);
    cudaFuncSetAttribute(attn_mma_kernel, cudaFuncAttributeMaxDynamicSharedMemorySize, A_SMEM);

    prep_all_kernel<<<PX_BLOCKS + PW_BLOCKS + PA_BLOCKS, 256>>>(x, W, a_src, a_dst);
    srcdst_kernel<<<(Bb * Nn) / 8, 256>>>(x);
    prep_pqrs_kernel<<<BHt, 1024>>>();
    proj_mma_kernel<<<dim3(8, 2, BHt), 256, P_SMEM>>>();
    attn_mma_kernel<<<dim3(8, 2, BHt), 256, A_SMEM>>>(out);
}

// round 16
// speedup vs baseline: 1.1602x; 1.0154x over previous
#include <cuda_runtime.h>
#include <cuda_fp16.h>
#include <cstdint>

#define Bb 8
#define Nn 1024
#define Ff 256
#define Hh 4
#define Uu 256
#define BHt (Bb * Hh)

#define STRIDE 40    // proj smem row stride in halves (80B)
#define VSTR 72      // attn V row stride in halves (144B)

// ---------------- device scratch (static, no allocation) ----------------
__device__ __half g_xh[(size_t)Bb * Nn * Ff];       // x fp16 [b][n][f]
__device__ __half g_vt[(size_t)BHt * Uu * Nn];      // h^T fp16 [bh][u][n]
__device__ __half g_wt[Hh * Uu * Ff];               // W^T fp16 [h][u][f]
__device__ float g_wa_src[Hh * Ff];                 // (W @ a_src)[h][f] fp32
__device__ float g_wa_dst[Hh * Ff];
__device__ float g_src[BHt * Nn];                   // exact fp32 logits
__device__ float g_dst[BHt * Nn];
__device__ __half g_Qh[BHt * Nn];
__device__ __half g_Sh[BHt * Nn];
__device__ __half g_Dh[BHt * Nn];
__device__ __half g_Ph[BHt * Nn];
__device__ __half g_Rh[BHt * Nn];
__device__ __half g_Th[BHt * Nn];

// ---------------- PTX helpers ----------------
__device__ __forceinline__ void mma16816(float* c, const uint32_t* a, uint32_t b0, uint32_t b1) {
    asm volatile(
        "mma.sync.aligned.m16n8k16.row.col.f32.f16.f16.f32 "
        "{%0,%1,%2,%3}, {%4,%5,%6,%7}, {%8,%9}, {%0,%1,%2,%3};"
        : "+f"(c[0]), "+f"(c[1]), "+f"(c[2]), "+f"(c[3])
        : "r"(a[0]), "r"(a[1]), "r"(a[2]), "r"(a[3]), "r"(b0), "r"(b1));
}
__device__ __forceinline__ void ldm_x4(uint32_t* r, uint32_t addr) {
    asm volatile("ldmatrix.sync.aligned.m8n8.x4.shared.b16 {%0,%1,%2,%3}, [%4];"
                 : "=r"(r[0]), "=r"(r[1]), "=r"(r[2]), "=r"(r[3]) : "r"(addr));
}
__device__ __forceinline__ void cp16(uint32_t dst, const void* src) {
    asm volatile("cp.async.ca.shared.global [%0], [%1], 16;" :: "r"(dst), "l"(src));
}
__device__ __forceinline__ void cp_commit() { asm volatile("cp.async.commit_group;"); }
template <int N> __device__ __forceinline__ void cp_wait() {
    asm volatile("cp.async.wait_group %0;" :: "n"(N));
}

// ================== fused prep: x->fp16 | W^T fp16 | Wa fp32 ==================
#define PX_BLOCKS 2048
#define PW_BLOCKS 1024
#define PA_BLOCKS 128

__global__ __launch_bounds__(256) void prep_all_kernel(const float* __restrict__ x,
                                                       const float* __restrict__ W,
                                                       const float* __restrict__ a_src,
                                                       const float* __restrict__ a_dst) {
    int blk = blockIdx.x;
    if (blk < PX_BLOCKS) {
        int idx = blk * 256 + threadIdx.x;
        float4 v = ((const float4*)x)[idx];
        ((__half2*)g_xh)[idx * 2]     = __floats2half2_rn(v.x, v.y);
        ((__half2*)g_xh)[idx * 2 + 1] = __floats2half2_rn(v.z, v.w);
    } else if (blk < PX_BLOCKS + PW_BLOCKS) {
        int idx = (blk - PX_BLOCKS) * 256 + threadIdx.x;
        int f = idx & 255, u = (idx >> 8) & 255, h = idx >> 16;
        float w = W[((size_t)(h * 256 + f)) * 256 + u];
        g_wt[((size_t)(h * 256 + u)) * 256 + f] = __float2half_rn(w);
    } else {
        int warp = threadIdx.x >> 5, lane = threadIdx.x & 31;
        int rowid = (blk - PX_BLOCKS - PW_BLOCKS) * 8 + warp;   // [0, H*F)
        int h = rowid >> 8;
        const float* wrow = W + (size_t)rowid * 256;
        const float* as = a_src + h * 256;
        const float* ad = a_dst + h * 256;
        float s1 = 0.f, s2 = 0.f;
#pragma unroll
        for (int u = lane * 4; u < 256; u += 128) {
            float4 w = *(const float4*)&wrow[u];
            float4 p = *(const float4*)&as[u];
            float4 q = *(const float4*)&ad[u];
            s1 += w.x * p.x + w.y * p.y + w.z * p.z + w.w * p.w;
            s2 += w.x * q.x + w.y * q.y + w.z * q.z + w.w * q.w;
        }
#pragma unroll
        for (int o = 16; o > 0; o >>= 1) {
            s1 += __shfl_down_sync(0xffffffffu, s1, o);
            s2 += __shfl_down_sync(0xffffffffu, s2, o);
        }
        if (lane == 0) { g_wa_src[rowid] = s1; g_wa_dst[rowid] = s2; }
    }
}

// ================== src/dst: exact fp32 GEMV from x, Wa staged in smem ==================
__global__ __launch_bounds__(256) void srcdst_kernel(const float* __restrict__ x) {
    __shared__ float sWs[Hh * Ff];
    __shared__ float sWd[Hh * Ff];
    int tid = threadIdx.x;
#pragma unroll
    for (int k = 0; k < 4; k++) {
        sWs[tid + k * 256] = g_wa_src[tid + k * 256];
        sWd[tid + k * 256] = g_wa_dst[tid + k * 256];
    }
    __syncthreads();

    int warp = tid >> 5, lane = tid & 31;
    int row = blockIdx.x * 8 + warp;
    int b = row >> 10, n = row & 1023;
    const float* xr = x + (size_t)row * Ff;

    float xv[8];
    float4 v0 = *(const float4*)&xr[lane * 4];
    float4 v1 = *(const float4*)&xr[128 + lane * 4];
    xv[0] = v0.x; xv[1] = v0.y; xv[2] = v0.z; xv[3] = v0.w;
    xv[4] = v1.x; xv[5] = v1.y; xv[6] = v1.z; xv[7] = v1.w;

#pragma unroll
    for (int h = 0; h < Hh; h++) {
        const float* ws = sWs + h * Ff;
        const float* wd = sWd + h * Ff;
        float4 p0 = *(const float4*)&ws[lane * 4];
        float4 p1 = *(const float4*)&ws[128 + lane * 4];
        float4 q0 = *(const float4*)&wd[lane * 4];
        float4 q1 = *(const float4*)&wd[128 + lane * 4];
        float s1 = xv[0]*p0.x + xv[1]*p0.y + xv[2]*p0.z + xv[3]*p0.w
                 + xv[4]*p1.x + xv[5]*p1.y + xv[6]*p1.z + xv[7]*p1.w;
        float s2 = xv[0]*q0.x + xv[1]*q0.y + xv[2]*q0.z + xv[3]*q0.w
                 + xv[4]*q1.x + xv[5]*q1.y + xv[6]*q1.z + xv[7]*q1.w;
#pragma unroll
        for (int o = 16; o > 0; o >>= 1) {
            s1 += __shfl_down_sync(0xffffffffu, s1, o);
            s2 += __shfl_down_sync(0xffffffffu, s2, o);
        }
        if (lane == 0) {
            int bh = b * Hh + h;
            g_src[bh * Nn + n] = s1;
            g_dst[bh * Nn + n] = s2;
        }
    }
}

// ================== proj: h = xh @ WT — single fp16 term, 2 CTAs/SM ==================
#define PBUF (2 * 128 * STRIDE * 2)                    // 20480 B per buffer
#define P_SMEM (2 * PBUF)

__global__ __launch_bounds__(256, 2) void proj_mma_kernel() {
    extern __shared__ __align__(16) char dyn[];

    int tid = threadIdx.x;
    int warp = tid >> 5, lane = tid & 31;
    int warp_m = warp & 3, warp_n = warp >> 2;
    int bh = blockIdx.z, b = bh >> 2, h = bh & 3;
    int i0 = blockIdx.x * 128, u0 = blockIdx.y * 128;

    uint32_t smb = (uint32_t)__cvta_generic_to_shared(dyn);
    int row = tid >> 1, seg = tid & 1;

    auto issue = [&](int st, int bufi) {
        int f0 = st * 32;
        uint32_t base = smb + bufi * PBUF + row * (STRIDE * 2) + seg * 32;
        const __half* gA = g_xh + ((size_t)(b * Nn + i0 + row)) * Ff + f0 + seg * 16;
        const __half* gW = g_wt + ((size_t)(h * 256 + u0 + row)) * 256 + f0 + seg * 16;
        cp16(base, gA);          cp16(base + 16, gA + 8);
        cp16(base + 10240, gW);  cp16(base + 10240 + 16, gW + 8);
    };

    float acc[2][8][4];
#pragma unroll
    for (int mt = 0; mt < 2; mt++)
#pragma unroll
        for (int nt = 0; nt < 8; nt++)
#pragma unroll
            for (int q = 0; q < 4; q++) acc[mt][nt][q] = 0.f;

    issue(0, 0);
    cp_commit();

    uint32_t a_off = (uint32_t)(warp_m * 32 + (lane & 15)) * (STRIDE * 2) + ((lane >> 4) * 8) * 2;
    uint32_t b_off = (uint32_t)(warp_n * 64 + (lane & 7)) * (STRIDE * 2) + ((lane >> 3) * 8) * 2;

    for (int st = 0; st < 8; st++) {
        if (st < 7) { issue(st + 1, (st + 1) & 1); cp_commit(); cp_wait<1>(); }
        else cp_wait<0>();
        __syncthreads();

        uint32_t bb = smb + (st & 1) * PBUF;
        uint32_t aH[2][2][4];
#pragma unroll
        for (int mt = 0; mt < 2; mt++)
#pragma unroll
            for (int kk = 0; kk < 2; kk++)
                ldm_x4(aH[mt][kk], bb + a_off + mt * 16 * (STRIDE * 2) + kk * 32);
#pragma unroll
        for (int nt = 0; nt < 8; nt++) {
            uint32_t bH[4];
            ldm_x4(bH, bb + 10240 + b_off + nt * 8 * (STRIDE * 2));
#pragma unroll
            for (int kk = 0; kk < 2; kk++)
#pragma unroll
                for (int mt = 0; mt < 2; mt++)
                    mma16816(acc[mt][nt], aH[mt][kk], bH[2 * kk], bH[2 * kk + 1]);
        }
        __syncthreads();
    }

    // ---- epilogue: fp16 transpose restage -> g_vt [u][n] ----
    __half (*tr)[136] = (__half (*)[136])dyn;
#pragma unroll
    for (int mt = 0; mt < 2; mt++) {
        int i_loc = warp_m * 32 + mt * 16 + (lane >> 2);
#pragma unroll
        for (int nt = 0; nt < 8; nt++) {
            int u_loc = warp_n * 64 + nt * 8 + (lane & 3) * 2;
            tr[u_loc][i_loc]         = __float2half_rn(acc[mt][nt][0]);
            tr[u_loc + 1][i_loc]     = __float2half_rn(acc[mt][nt][1]);
            tr[u_loc][i_loc + 8]     = __float2half_rn(acc[mt][nt][2]);
            tr[u_loc + 1][i_loc + 8] = __float2half_rn(acc[mt][nt][3]);
        }
    }
    __syncthreads();
    {
        const float4* srcp = (const float4*)&tr[row][seg * 64];
        float4* dstp = (float4*)&g_vt[((size_t)bh * Uu + u0 + row) * Nn + i0 + seg * 64];
#pragma unroll
        for (int k = 0; k < 8; k++) dstp[k] = srcp[k];
    }
}

// ================== prep: P/Q/R/S/D/thr fp16 per (b,h) from exact logits ==================
__global__ __launch_bounds__(1024) void prep_pqrs_kernel() {
    __shared__ float red[1024];
    int bh = blockIdx.x, tid = threadIdx.x;
    int row = bh * Nn + tid;
    float d = g_dst[row];
    float sv = g_src[row];
    red[tid] = d;
    __syncthreads();
    for (int s = 512; s > 0; s >>= 1) {
        if (tid < s) red[tid] = fmaxf(red[tid], red[tid + s]);
        __syncthreads();
    }
    float dmax = red[0];
    g_Qh[row] = __float2half_rn(__expf(d - dmax));
    g_Sh[row] = __float2half_rn(__expf(0.2f * (d - dmax)));
    g_Dh[row] = __float2half_rn(d);
    float T = sv + dmax;
    float m = fmaxf(T, 0.2f * T);
    g_Ph[row] = __float2half_rn(__expf(T - m));
    g_Rh[row] = __float2half_rn(__expf(0.2f * T - m));
    g_Th[row] = __float2half_rn(-sv);
}

// ================== attention (R13, unchanged): KT=64, triple buffer ==================
#define VBUF (128 * VSTR * 2)                          // 18432 B
#define A_SMEM (3 * VBUF + 6144 + 1024)

__global__ __launch_bounds__(256) void attn_mma_kernel(float* __restrict__ out) {
    extern __shared__ __align__(16) char adyn[];
    __half* Dsh = (__half*)(adyn + 3 * VBUF);
    __half* Qsh = Dsh + Nn;
    __half* Ssh = Qsh + Nn;
    __half* Pn = Ssh + Nn;
    __half* Rn = Pn + 128;
    __half* Tn = Rn + 128;

    int tid = threadIdx.x;
    int warp = tid >> 5, lane = tid & 31;
    int warp_m = warp & 3, warp_n = warp >> 2;
    int bh = blockIdx.z, b = bh >> 2, h = bh & 3;
    int i0 = blockIdx.x * 128, u0 = blockIdx.y * 128;

    for (int j = tid; j < Nn; j += 256) {
        Dsh[j] = g_Dh[bh * Nn + j];
        Qsh[j] = g_Qh[bh * Nn + j];
        Ssh[j] = g_Sh[bh * Nn + j];
    }
    if (tid < 128) {
        Pn[tid] = g_Ph[bh * Nn + i0 + tid];
        Rn[tid] = g_Rh[bh * Nn + i0 + tid];
        Tn[tid] = g_Th[bh * Nn + i0 + tid];
    }

    int row = tid >> 1, seg = tid & 1;
    uint32_t vt0 = (uint32_t)__cvta_generic_to_shared(adyn);

    auto issue = [&](int st, int bufi) {
        int j0 = st * 64;
        uint32_t d = vt0 + bufi * VBUF + row * (VSTR * 2) + seg * 64;
        const __half* g = g_vt + ((size_t)bh * Uu + u0 + row) * Nn + j0 + seg * 32;
        cp16(d, g);           cp16(d + 16, g + 8);
        cp16(d + 32, g + 16); cp16(d + 48, g + 24);
    };

    float acc[2][8][4];
#pragma unroll
    for (int mt = 0; mt < 2; mt++)
#pragma unroll
        for (int nt = 0; nt < 8; nt++)
#pragma unroll
            for (int q = 0; q < 4; q++) acc[mt][nt][q] = 0.f;
    float rs[4] = {0.f, 0.f, 0.f, 0.f};

    issue(0, 0); cp_commit();
    issue(1, 1); cp_commit();
    __syncthreads();

    __half2 Pv[4], Rv[4], Tv[4];
#pragma unroll
    for (int q = 0; q < 4; q++) {
        int r = warp_m * 32 + (q >> 1) * 16 + (q & 1) * 8 + (lane >> 2);
        Pv[q] = __half2half2(Pn[r]);
        Rv[q] = __half2half2(Rn[r]);
        Tv[q] = __half2half2(Tn[r]);
    }

    uint32_t b_off = (uint32_t)(warp_n * 64 + (lane & 7)) * (VSTR * 2) + ((lane >> 3) * 8) * 2;

    for (int st = 0; st < 16; st++) {
        if (st < 15) cp_wait<1>(); else cp_wait<0>();
        __syncthreads();
        if (st + 2 < 16) { issue(st + 2, (st + 2) % 3); cp_commit(); }

        uint32_t bb = vt0 + (st % 3) * VBUF;

#pragma unroll
        for (int kp = 0; kp < 2; kp++) {
            uint32_t bfr[8][4];
#pragma unroll
            for (int nt = 0; nt < 8; nt++)
                ldm_x4(bfr[nt], bb + b_off + nt * 8 * (VSTR * 2) + kp * 64);

#pragma unroll
            for (int kk = 0; kk < 2; kk++) {
                int c = st * 64 + kp * 32 + kk * 16 + (lane & 3) * 2;
                __half2 Qa = *(const __half2*)&Qsh[c], Qb = *(const __half2*)&Qsh[c + 8];
                __half2 Sa = *(const __half2*)&Ssh[c], Sb = *(const __half2*)&Ssh[c + 8];
                __half2 Da = *(const __half2*)&Dsh[c], Db = *(const __half2*)&Dsh[c + 8];

                uint32_t aW[2][4];
#pragma unroll
                for (int mt = 0; mt < 2; mt++) {
#pragma unroll
                    for (int dq = 0; dq < 2; dq++) {
                        int q = mt * 2 + dq;
                        __half2 mA = __hge2(Da, Tv[q]);
                        __half2 wPa = __hmul2(Pv[q], Qa);
                        __half2 wRa = __hmul2(Rv[q], Sa);
                        __half2 wa = __hfma2(__hsub2(wPa, wRa), mA, wRa);
                        __half2 mB = __hge2(Db, Tv[q]);
                        __half2 wPb = __hmul2(Pv[q], Qb);
                        __half2 wRb = __hmul2(Rv[q], Sb);
                        __half2 wb = __hfma2(__hsub2(wPb, wRb), mB, wRb);
                        aW[mt][dq]     = *reinterpret_cast<uint32_t*>(&wa);
                        aW[mt][dq + 2] = *reinterpret_cast<uint32_t*>(&wb);
                        __half2 hsum = __hadd2(wa, wb);
                        float2 f = __half22float2(hsum);
                        rs[q] += f.x + f.y;
                    }
                }
#pragma unroll
                for (int nt = 0; nt < 8; nt++)
#pragma unroll
                    for (int mt = 0; mt < 2; mt++)
                        mma16816(acc[mt][nt], aW[mt], bfr[nt][2 * kk], bfr[nt][2 * kk + 1]);
            }
        }
    }

#pragma unroll
    for (int q = 0; q < 4; q++) {
        rs[q] += __shfl_xor_sync(0xffffffffu, rs[q], 1);
        rs[q] += __shfl_xor_sync(0xffffffffu, rs[q], 2);
        rs[q] = 1.0f / rs[q];
    }

#pragma unroll
    for (int mt = 0; mt < 2; mt++) {
        int i_lo = i0 + warp_m * 32 + mt * 16 + (lane >> 2);
        float inv0 = rs[mt * 2], inv1 = rs[mt * 2 + 1];
#pragma unroll
        for (int nt = 0; nt < 8; nt++) {
            int u = u0 + warp_n * 64 + nt * 8 + (lane & 3) * 2;
            size_t o0 = ((size_t)(b * Nn + i_lo)) * (Hh * Uu) + h * Uu + u;
            size_t o1 = ((size_t)(b * Nn + i_lo + 8)) * (Hh * Uu) + h * Uu + u;
            *(float2*)&out[o0] = make_float2(acc[mt][nt][0] * inv0, acc[mt][nt][1] * inv0);
            *(float2*)&out[o1] = make_float2(acc[mt][nt][2] * inv1, acc[mt][nt][3] * inv1);
        }
    }
}

// ---------------------------------------------------------------------------
extern "C" void kernel_launch(void* const* d_in, const int* in_sizes, int n_in,
                              void* d_out, int out_size) {
    (void)in_sizes; (void)n_in; (void)out_size;
    const float* x     = (const float*)d_in[0];
    const float* W     = (const float*)d_in[1];
    const float* a_src = (const float*)d_in[2];
    const float* a_dst = (const float*)d_in[3];
    float* out = (float*)d_out;

    cudaFuncSetAttribute(proj_mma_kernel, cudaFuncAttributeMaxDynamicSharedMemorySize, P_SMEM);
    cudaFuncSetAttribute(attn_mma_kernel, cudaFuncAttributeMaxDynamicSharedMemorySize, A_SMEM);

    prep_all_kernel<<<PX_BLOCKS + PW_BLOCKS + PA_BLOCKS, 256>>>(x, W, a_src, a_dst);
    srcdst_kernel<<<(Bb * Nn) / 8, 256>>>(x);
    prep_pqrs_kernel<<<BHt, 1024>>>();
    proj_mma_kernel<<<dim3(8, 2, BHt), 256, P_SMEM>>>();
    attn_mma_kernel<<<dim3(8, 2, BHt), 256, A_SMEM>>>(out);
}